// round 5
// baseline (speedup 1.0000x reference)
#include <cuda_runtime.h>
#include <cstdint>
#include <math.h>

// ---------------------------------------------------------------- constants
#define BB 4
#define TT 4096
#define DD 1024
#define MM (BB * TT)            // 16384
#define TOTL ((size_t)MM * DD)  // 16777216
#define BD (BB * DD)            // 4096
#define CH 64                   // scan chunks per sequence
#define CLEN (TT / CH)          // 64

#define LOG8F 2.0794415416798357f

// ---------------------------------------------------------------- scratch
__device__ float g_a[MM * DD];      // decay a
__device__ float g_u[MM * DD];      // input term u
__device__ float g_P[BD * CH];
__device__ float g_Q[BD * CH];
__device__ float g_S[BD * CH];

// ---------------------------------------------------------------- tf32 utils
__device__ __forceinline__ float tf32r(float x) {
    uint32_t o;
    asm("cvt.rna.tf32.f32 %0, %1;" : "=r"(o) : "f"(x));
    return __uint_as_float(o);
}
__device__ __forceinline__ float4 cvt4(float4 v) {
    v.x = tf32r(v.x); v.y = tf32r(v.y); v.z = tf32r(v.z); v.w = tf32r(v.w);
    return v;
}

__device__ __forceinline__ void mma_tf32(float* d, const uint32_t* a, const uint32_t* b) {
    asm volatile(
        "mma.sync.aligned.m16n8k8.row.col.f32.tf32.tf32.f32 "
        "{%0,%1,%2,%3}, {%4,%5,%6,%7}, {%8,%9}, {%0,%1,%2,%3};"
        : "+f"(d[0]), "+f"(d[1]), "+f"(d[2]), "+f"(d[3])
        : "r"(a[0]), "r"(a[1]), "r"(a[2]), "r"(a[3]), "r"(b[0]), "r"(b[1]));
}

// ---------------------------------------------------------------- fused GEMM
// Computes zr=x@Wr^T, zi=x@Wi^T, zx=x@Wx^T for one 128x128 tile with a SHARED
// A tile, then applies the full gate math in the epilogue:
//   a = sigmoid(-log8 * sigmoid(zr + br)); u = sqrt(1-a^2) * sigmoid(zi+bi) * zx
// 128x128x32 CTA tile, 8 warps (2Mx4N), 64x32 warp tile per weight matrix.
#define BM 128
#define BN 128
#define BK 32
#define NK (DD / BK)            // 32
#define RS 36                   // padded row stride (floats) -> conflict-free
#define A_STRIDE (128 * RS)     // floats per stage
#define SMEM_BYTES ((2 * A_STRIDE + 3 * 2 * A_STRIDE) * 4)   // 147456

__global__ void __launch_bounds__(256, 1)
rglru_gemm_gate(const float* __restrict__ A,
                const float* __restrict__ Wr, const float* __restrict__ Wi,
                const float* __restrict__ Wx,
                const float* __restrict__ br, const float* __restrict__ bi)
{
    extern __shared__ float smem[];
    float* As = smem;                       // [2][128][RS]
    float* Bs = smem + 2 * A_STRIDE;        // [3][2][128][RS]

    const int tid = threadIdx.x;
    const int wid = tid >> 5;
    const int lane = tid & 31;
    const int r = lane >> 2;          // 0..7
    const int c = lane & 3;           // 0..3
    const int mw = (wid >> 2) * 64;   // warp m offset
    const int nw = (wid & 3) * 32;    // warp n offset
    const int bm = blockIdx.y * BM;
    const int bn = blockIdx.x * BN;

    float acc[3][4][4][4];
#pragma unroll
    for (int w = 0; w < 3; w++)
#pragma unroll
        for (int i = 0; i < 4; i++)
#pragma unroll
            for (int j = 0; j < 4; j++)
#pragma unroll
                for (int q = 0; q < 4; q++) acc[w][i][j][q] = 0.f;

    const float* Ws[3] = {Wr, Wi, Wx};

    // prologue: stage 0. mapping: u = tid + 256*i -> row=u>>3 (0..127), col4=u&7
#pragma unroll
    for (int i = 0; i < 4; i++) {
        const int u = tid + 256 * i;
        const int row = u >> 3, col4 = u & 7;
        float4 va = cvt4(*(const float4*)(A + (size_t)(bm + row) * DD + col4 * 4));
        *(float4*)&As[row * RS + col4 * 4] = va;
#pragma unroll
        for (int w = 0; w < 3; w++) {
            float4 vb = cvt4(*(const float4*)(Ws[w] + (size_t)(bn + row) * DD + col4 * 4));
            *(float4*)&Bs[(w * 2) * A_STRIDE + row * RS + col4 * 4] = vb;
        }
    }
    __syncthreads();

    for (int kt = 0; kt < NK; kt++) {
        const int s = kt & 1;
        if (kt + 1 < NK) {
            const int k0 = (kt + 1) * BK;
#pragma unroll
            for (int i = 0; i < 4; i++) {
                const int u = tid + 256 * i;
                const int row = u >> 3, col4 = u & 7;
                float4 va = cvt4(*(const float4*)(A + (size_t)(bm + row) * DD + k0 + col4 * 4));
                *(float4*)&As[(s ^ 1) * A_STRIDE + row * RS + col4 * 4] = va;
#pragma unroll
                for (int w = 0; w < 3; w++) {
                    float4 vb = cvt4(*(const float4*)(Ws[w] + (size_t)(bn + row) * DD + k0 + col4 * 4));
                    *(float4*)&Bs[(w * 2 + (s ^ 1)) * A_STRIDE + row * RS + col4 * 4] = vb;
                }
            }
        }
#pragma unroll
        for (int kk = 0; kk < BK; kk += 8) {
            uint32_t af[4][4];
#pragma unroll
            for (int mi = 0; mi < 4; mi++) {
                const float* pa = &As[s * A_STRIDE + (mw + mi * 16 + r) * RS + kk + c];
                af[mi][0] = __float_as_uint(pa[0]);
                af[mi][1] = __float_as_uint(pa[8 * RS]);
                af[mi][2] = __float_as_uint(pa[4]);
                af[mi][3] = __float_as_uint(pa[8 * RS + 4]);
            }
#pragma unroll
            for (int w = 0; w < 3; w++) {
                const float* bw = &Bs[(w * 2 + s) * A_STRIDE];
#pragma unroll
                for (int ni = 0; ni < 4; ni++) {
                    uint32_t bf[2];
                    const float* pb = &bw[(nw + ni * 8 + r) * RS + kk + c];
                    bf[0] = __float_as_uint(pb[0]);
                    bf[1] = __float_as_uint(pb[4]);
#pragma unroll
                    for (int mi = 0; mi < 4; mi++)
                        mma_tf32(acc[w][mi][ni], af[mi], bf);
                }
            }
        }
        __syncthreads();
    }

    // ---- epilogue: gate math from registers -> g_a, g_u
#pragma unroll
    for (int mi = 0; mi < 4; mi++) {
#pragma unroll
        for (int ni = 0; ni < 4; ni++) {
            const int m0 = bm + mw + mi * 16 + r;
            const int n  = bn + nw + ni * 8 + c * 2;
            const float br0 = __ldg(br + n), br1 = __ldg(br + n + 1);
            const float bi0 = __ldg(bi + n), bi1 = __ldg(bi + n + 1);
#pragma unroll
            for (int h = 0; h < 2; h++) {
                const size_t idx = (size_t)(m0 + 8 * h) * DD + n;
                float av[2], uv[2];
#pragma unroll
                for (int q = 0; q < 2; q++) {
                    const float zr = acc[0][mi][ni][h * 2 + q] + (q ? br1 : br0);
                    const float zi = acc[1][mi][ni][h * 2 + q] + (q ? bi1 : bi0);
                    const float zx = acc[2][mi][ni][h * 2 + q];
                    const float rr = 1.f / (1.f + __expf(-zr));
                    // exp(-softplus(log8*r)) == sigmoid(-log8*r)
                    const float a = 1.f / (1.f + __expf(LOG8F * rr));
                    const float g = sqrtf(fmaxf(1.f - a * a, 1e-6f));
                    const float iv = 1.f / (1.f + __expf(-zi));
                    av[q] = a;
                    uv[q] = g * iv * zx;
                }
                *(float2*)&g_a[idx] = make_float2(av[0], av[1]);
                *(float2*)&g_u[idx] = make_float2(uv[0], uv[1]);
            }
        }
    }
}

// ---------------------------------------------------------------- scan (3-pass)
__global__ void __launch_bounds__(256) scan_pass1() {
    const int g = blockIdx.x * 256 + threadIdx.x;        // 0..BD*CH-1
    const int d = g & (DD - 1);
    const int ch = (g >> 10) & (CH - 1);
    const int b = g >> 16;                                // 10 + 6 bits
    const size_t base = (size_t)b * TT * DD + (size_t)ch * CLEN * DD + d;
    float P = 1.f, Q = 0.f;
#pragma unroll 8
    for (int j = 0; j < CLEN; j++) {
        const float a = g_a[base + (size_t)j * DD];
        const float u = g_u[base + (size_t)j * DD];
        P *= a;
        Q = fmaf(a, Q, u);
    }
    g_P[g] = P;
    g_Q[g] = Q;
}

__global__ void __launch_bounds__(256) scan_pass2(const float* __restrict__ h0,
                                                  float* __restrict__ hlast) {
    const int bd = blockIdx.x * 256 + threadIdx.x;       // 0..4095
    const int b = bd >> 10, d = bd & (DD - 1);
    float S = h0[bd];
#pragma unroll
    for (int ch = 0; ch < CH; ch++) {
        const int idx = ((b * CH + ch) << 10) | d;
        g_S[idx] = S;
        S = fmaf(g_P[idx], S, g_Q[idx]);
    }
    hlast[bd] = S;
}

__global__ void __launch_bounds__(256) scan_pass3(float* __restrict__ out) {
    const int g = blockIdx.x * 256 + threadIdx.x;
    const int d = g & (DD - 1);
    const int ch = (g >> 10) & (CH - 1);
    const int b = g >> 16;
    const size_t base = (size_t)b * TT * DD + (size_t)ch * CLEN * DD + d;
    float h = g_S[g];
#pragma unroll 8
    for (int j = 0; j < CLEN; j++) {
        h = fmaf(g_a[base + (size_t)j * DD], h, g_u[base + (size_t)j * DD]);
        out[base + (size_t)j * DD] = h;
    }
}

// ---------------------------------------------------------------- launch
extern "C" void kernel_launch(void* const* d_in, const int* in_sizes, int n_in,
                              void* d_out, int out_size)
{
    const float* x   = (const float*)d_in[0];
    const float* h0  = (const float*)d_in[1];
    const float* W_r = (const float*)d_in[2];
    const float* b_r = (const float*)d_in[3];
    const float* W_i = (const float*)d_in[4];
    const float* b_i = (const float*)d_in[5];
    const float* W_x = (const float*)d_in[6];
    float* out = (float*)d_out;

    cudaFuncSetAttribute(rglru_gemm_gate,
                         cudaFuncAttributeMaxDynamicSharedMemorySize, SMEM_BYTES);

    dim3 grid(DD / BN, MM / BM);   // (8, 128)
    rglru_gemm_gate<<<grid, 256, SMEM_BYTES>>>(x, W_r, W_i, W_x, b_r, b_i);

    scan_pass1<<<(BD * CH) / 256, 256>>>();
    scan_pass2<<<BD / 256, 256>>>(h0, out + TOTL);
    scan_pass3<<<(BD * CH) / 256, 256>>>(out);
}

// round 6
// speedup vs baseline: 1.2696x; 1.2696x over previous
#include <cuda_runtime.h>
#include <cuda_fp16.h>
#include <cstdint>
#include <math.h>

// ---------------------------------------------------------------- constants
#define BB 4
#define TT 4096
#define DD 1024
#define MM (BB * TT)            // 16384
#define TOTL ((size_t)MM * DD)  // 16777216
#define BD (BB * DD)            // 4096
#define CH 64                   // scan chunks per sequence
#define CLEN (TT / CH)          // 64

#define LOG8F 2.0794415416798357f

// ---------------------------------------------------------------- scratch
__device__ float g_a[MM * DD];      // raw zr  -> a
__device__ float g_u[MM * DD];      // raw zi  -> u
__device__ float g_P[BD * CH];
__device__ float g_Q[BD * CH];
__device__ float g_S[BD * CH];

// ---------------------------------------------------------------- utils
__device__ __forceinline__ float tf32r(float x) {
    uint32_t o;
    asm("cvt.rna.tf32.f32 %0, %1;" : "=r"(o) : "f"(x));
    return __uint_as_float(o);
}
__device__ __forceinline__ float4 cvt4(float4 v) {
    v.x = tf32r(v.x); v.y = tf32r(v.y); v.z = tf32r(v.z); v.w = tf32r(v.w);
    return v;
}

__device__ __forceinline__ void mma_tf32(float* d, const uint32_t* a, const uint32_t* b) {
    asm volatile(
        "mma.sync.aligned.m16n8k8.row.col.f32.tf32.tf32.f32 "
        "{%0,%1,%2,%3}, {%4,%5,%6,%7}, {%8,%9}, {%0,%1,%2,%3};"
        : "+f"(d[0]), "+f"(d[1]), "+f"(d[2]), "+f"(d[3])
        : "r"(a[0]), "r"(a[1]), "r"(a[2]), "r"(a[3]), "r"(b[0]), "r"(b[1]));
}
__device__ __forceinline__ void mma_f16(float* d, const uint32_t* a, const uint32_t* b) {
    asm volatile(
        "mma.sync.aligned.m16n8k16.row.col.f32.f16.f16.f32 "
        "{%0,%1,%2,%3}, {%4,%5,%6,%7}, {%8,%9}, {%0,%1,%2,%3};"
        : "+f"(d[0]), "+f"(d[1]), "+f"(d[2]), "+f"(d[3])
        : "r"(a[0]), "r"(a[1]), "r"(a[2]), "r"(a[3]), "r"(b[0]), "r"(b[1]));
}

// ================================================================ tf32 GEMM
// C[m,n] = sum_k A[m,k]*W[n,k] (NT). 128x128x32 tile, 8 warps (2Mx4N), 64x32
// warp tile. GATE=1: reads raw zr/zi from g_a/g_u, applies gate, overwrites.
#define BM 128
#define BN 128
#define BK 32
#define NK (DD / BK)            // 32
#define RS 36
#define SMEM_T ((2 * 2 * 128 * RS) * 4)   // 73728

#define SA(s, m, k) As[((s) * 128 + (m)) * RS + (k)]
#define SB(s, n, k) Bs[((s) * 128 + (n)) * RS + (k)]

template <int GATE>
__global__ void __launch_bounds__(256, 2)
gemm_tf32(const float* __restrict__ A, const float* __restrict__ W,
          float* __restrict__ C,
          const float* __restrict__ br, const float* __restrict__ bi)
{
    extern __shared__ float smem[];
    float* As = smem;
    float* Bs = smem + 2 * 128 * RS;

    const int tid = threadIdx.x;
    const int wid = tid >> 5;
    const int lane = tid & 31;
    const int r = lane >> 2;
    const int c = lane & 3;
    const int mw = (wid >> 2) * 64;
    const int nw = (wid & 3) * 32;
    const int bm = blockIdx.y * BM;
    const int bn = blockIdx.x * BN;

    float acc[4][4][4];
#pragma unroll
    for (int i = 0; i < 4; i++)
#pragma unroll
        for (int j = 0; j < 4; j++)
#pragma unroll
            for (int q = 0; q < 4; q++) acc[i][j][q] = 0.f;

#pragma unroll
    for (int i = 0; i < 4; i++) {
        const int u = tid + 256 * i;
        const int row = u >> 3, col4 = u & 7;
        *(float4*)&SA(0, row, col4 * 4) =
            cvt4(*(const float4*)(A + (size_t)(bm + row) * DD + col4 * 4));
        *(float4*)&SB(0, row, col4 * 4) =
            cvt4(*(const float4*)(W + (size_t)(bn + row) * DD + col4 * 4));
    }
    __syncthreads();

    for (int kt = 0; kt < NK; kt++) {
        const int s = kt & 1;
        if (kt + 1 < NK) {
            const int k0 = (kt + 1) * BK;
#pragma unroll
            for (int i = 0; i < 4; i++) {
                const int u = tid + 256 * i;
                const int row = u >> 3, col4 = u & 7;
                *(float4*)&SA(s ^ 1, row, col4 * 4) =
                    cvt4(*(const float4*)(A + (size_t)(bm + row) * DD + k0 + col4 * 4));
                *(float4*)&SB(s ^ 1, row, col4 * 4) =
                    cvt4(*(const float4*)(W + (size_t)(bn + row) * DD + k0 + col4 * 4));
            }
        }
#pragma unroll
        for (int kk = 0; kk < BK; kk += 8) {
            uint32_t af[4][4], bf[4][2];
#pragma unroll
            for (int mi = 0; mi < 4; mi++) {
                const float* pa = &SA(s, mw + mi * 16 + r, kk + c);
                af[mi][0] = __float_as_uint(pa[0]);
                af[mi][1] = __float_as_uint(pa[8 * RS]);
                af[mi][2] = __float_as_uint(pa[4]);
                af[mi][3] = __float_as_uint(pa[8 * RS + 4]);
            }
#pragma unroll
            for (int ni = 0; ni < 4; ni++) {
                const float* pb = &SB(s, nw + ni * 8 + r, kk + c);
                bf[ni][0] = __float_as_uint(pb[0]);
                bf[ni][1] = __float_as_uint(pb[4]);
            }
#pragma unroll
            for (int mi = 0; mi < 4; mi++)
#pragma unroll
                for (int ni = 0; ni < 4; ni++)
                    mma_tf32(acc[mi][ni], af[mi], bf[ni]);
        }
        __syncthreads();
    }

#pragma unroll
    for (int mi = 0; mi < 4; mi++) {
#pragma unroll
        for (int ni = 0; ni < 4; ni++) {
            const int m0 = bm + mw + mi * 16 + r;
            const int n  = bn + nw + ni * 8 + c * 2;
            if (GATE == 0) {
                *(float2*)(C + (size_t)m0 * DD + n) =
                    make_float2(acc[mi][ni][0], acc[mi][ni][1]);
                *(float2*)(C + (size_t)(m0 + 8) * DD + n) =
                    make_float2(acc[mi][ni][2], acc[mi][ni][3]);
            } else {
                const float br0 = __ldg(br + n), br1 = __ldg(br + n + 1);
                const float bi0 = __ldg(bi + n), bi1 = __ldg(bi + n + 1);
#pragma unroll
                for (int h = 0; h < 2; h++) {
                    const size_t idx = (size_t)(m0 + 8 * h) * DD + n;
                    float2 zr = *(float2*)&g_a[idx];
                    float2 zi = *(float2*)&g_u[idx];
                    float av[2], uv[2];
#pragma unroll
                    for (int q = 0; q < 2; q++) {
                        const float zrv = (q ? zr.y : zr.x) + (q ? br1 : br0);
                        const float ziv = (q ? zi.y : zi.x) + (q ? bi1 : bi0);
                        const float rr = 1.f / (1.f + __expf(-zrv));
                        // exp(-softplus(log8*r)) == sigmoid(-log8*r)
                        const float a = 1.f / (1.f + __expf(LOG8F * rr));
                        const float g = sqrtf(fmaxf(1.f - a * a, 1e-6f));
                        const float iv = 1.f / (1.f + __expf(-ziv));
                        av[q] = a;
                        uv[q] = g * iv * acc[mi][ni][h * 2 + q];
                    }
                    *(float2*)&g_a[idx] = make_float2(av[0], av[1]);
                    *(float2*)&g_u[idx] = make_float2(uv[0], uv[1]);
                }
            }
        }
    }
}

// ================================================================ fp16 GEMM
// Same structure, half-precision inputs, m16n8k16 -> half the MMA/LDS work.
// Used only for the gate pre-activations (errors attenuated by gate slope).
#define RSH 40                         // halves per smem row (32 + 8 pad)
#define HSTAGE (128 * RSH)             // halves per stage
#define SMEM_H (2 * 2 * HSTAGE * 2)    // bytes = 40960

__global__ void __launch_bounds__(256, 2)
gemm_f16(const float* __restrict__ A, const float* __restrict__ W,
         float* __restrict__ C)
{
    extern __shared__ __half hsmem[];
    __half* As = hsmem;                  // [2][128][RSH]
    __half* Bs = hsmem + 2 * HSTAGE;

    const int tid = threadIdx.x;
    const int wid = tid >> 5;
    const int lane = tid & 31;
    const int r = lane >> 2;
    const int c = lane & 3;
    const int mw = (wid >> 2) * 64;
    const int nw = (wid & 3) * 32;
    const int bm = blockIdx.y * BM;
    const int bn = blockIdx.x * BN;

    float acc[4][4][4];
#pragma unroll
    for (int i = 0; i < 4; i++)
#pragma unroll
        for (int j = 0; j < 4; j++)
#pragma unroll
            for (int q = 0; q < 4; q++) acc[i][j][q] = 0.f;

    // load f32 -> half into smem. u = tid + 256*i -> row=u>>3, col4=u&7
#pragma unroll
    for (int i = 0; i < 4; i++) {
        const int u = tid + 256 * i;
        const int row = u >> 3, col4 = u & 7;
        float4 va = *(const float4*)(A + (size_t)(bm + row) * DD + col4 * 4);
        float4 vb = *(const float4*)(W + (size_t)(bn + row) * DD + col4 * 4);
        half2 a01 = __floats2half2_rn(va.x, va.y), a23 = __floats2half2_rn(va.z, va.w);
        half2 b01 = __floats2half2_rn(vb.x, vb.y), b23 = __floats2half2_rn(vb.z, vb.w);
        *(half2*)&As[row * RSH + col4 * 4]     = a01;
        *(half2*)&As[row * RSH + col4 * 4 + 2] = a23;
        *(half2*)&Bs[row * RSH + col4 * 4]     = b01;
        *(half2*)&Bs[row * RSH + col4 * 4 + 2] = b23;
    }
    __syncthreads();

    for (int kt = 0; kt < NK; kt++) {
        const int s = kt & 1;
        if (kt + 1 < NK) {
            const int k0 = (kt + 1) * BK;
#pragma unroll
            for (int i = 0; i < 4; i++) {
                const int u = tid + 256 * i;
                const int row = u >> 3, col4 = u & 7;
                float4 va = *(const float4*)(A + (size_t)(bm + row) * DD + k0 + col4 * 4);
                float4 vb = *(const float4*)(W + (size_t)(bn + row) * DD + k0 + col4 * 4);
                half2 a01 = __floats2half2_rn(va.x, va.y), a23 = __floats2half2_rn(va.z, va.w);
                half2 b01 = __floats2half2_rn(vb.x, vb.y), b23 = __floats2half2_rn(vb.z, vb.w);
                __half* as = &As[(s ^ 1) * HSTAGE + row * RSH + col4 * 4];
                __half* bs = &Bs[(s ^ 1) * HSTAGE + row * RSH + col4 * 4];
                *(half2*)as = a01; *(half2*)(as + 2) = a23;
                *(half2*)bs = b01; *(half2*)(bs + 2) = b23;
            }
        }
        // two k16 steps cover BK=32
#pragma unroll
        for (int kk = 0; kk < BK; kk += 16) {
            uint32_t af[4][4], bf[4][2];
#pragma unroll
            for (int mi = 0; mi < 4; mi++) {
                const __half* pa = &As[s * HSTAGE + (mw + mi * 16 + r) * RSH + kk + 2 * c];
                af[mi][0] = *(const uint32_t*)(pa);
                af[mi][1] = *(const uint32_t*)(pa + 8 * RSH);
                af[mi][2] = *(const uint32_t*)(pa + 8);
                af[mi][3] = *(const uint32_t*)(pa + 8 * RSH + 8);
            }
#pragma unroll
            for (int ni = 0; ni < 4; ni++) {
                const __half* pb = &Bs[s * HSTAGE + (nw + ni * 8 + r) * RSH + kk + 2 * c];
                bf[ni][0] = *(const uint32_t*)(pb);
                bf[ni][1] = *(const uint32_t*)(pb + 8);
            }
#pragma unroll
            for (int mi = 0; mi < 4; mi++)
#pragma unroll
                for (int ni = 0; ni < 4; ni++)
                    mma_f16(acc[mi][ni], af[mi], bf[ni]);
        }
        __syncthreads();
    }

#pragma unroll
    for (int mi = 0; mi < 4; mi++) {
#pragma unroll
        for (int ni = 0; ni < 4; ni++) {
            const int m0 = bm + mw + mi * 16 + r;
            const int n  = bn + nw + ni * 8 + c * 2;
            *(float2*)(C + (size_t)m0 * DD + n) =
                make_float2(acc[mi][ni][0], acc[mi][ni][1]);
            *(float2*)(C + (size_t)(m0 + 8) * DD + n) =
                make_float2(acc[mi][ni][2], acc[mi][ni][3]);
        }
    }
}

// ---------------------------------------------------------------- scan (3-pass)
__global__ void __launch_bounds__(256) scan_pass1() {
    const int g = blockIdx.x * 256 + threadIdx.x;
    const int d = g & (DD - 1);
    const int ch = (g >> 10) & (CH - 1);
    const int b = g >> 16;
    const size_t base = (size_t)b * TT * DD + (size_t)ch * CLEN * DD + d;
    float P = 1.f, Q = 0.f;
#pragma unroll 8
    for (int j = 0; j < CLEN; j++) {
        const float a = g_a[base + (size_t)j * DD];
        const float u = g_u[base + (size_t)j * DD];
        P *= a;
        Q = fmaf(a, Q, u);
    }
    g_P[g] = P;
    g_Q[g] = Q;
}

__global__ void __launch_bounds__(256) scan_pass2(const float* __restrict__ h0,
                                                  float* __restrict__ hlast) {
    const int bd = blockIdx.x * 256 + threadIdx.x;
    const int b = bd >> 10, d = bd & (DD - 1);
    float S = h0[bd];
#pragma unroll
    for (int ch = 0; ch < CH; ch++) {
        const int idx = ((b * CH + ch) << 10) | d;
        g_S[idx] = S;
        S = fmaf(g_P[idx], S, g_Q[idx]);
    }
    hlast[bd] = S;
}

__global__ void __launch_bounds__(256) scan_pass3(float* __restrict__ out) {
    const int g = blockIdx.x * 256 + threadIdx.x;
    const int d = g & (DD - 1);
    const int ch = (g >> 10) & (CH - 1);
    const int b = g >> 16;
    const size_t base = (size_t)b * TT * DD + (size_t)ch * CLEN * DD + d;
    float h = g_S[g];
#pragma unroll 8
    for (int j = 0; j < CLEN; j++) {
        h = fmaf(g_a[base + (size_t)j * DD], h, g_u[base + (size_t)j * DD]);
        out[base + (size_t)j * DD] = h;
    }
}

// ---------------------------------------------------------------- launch
extern "C" void kernel_launch(void* const* d_in, const int* in_sizes, int n_in,
                              void* d_out, int out_size)
{
    const float* x   = (const float*)d_in[0];
    const float* h0  = (const float*)d_in[1];
    const float* W_r = (const float*)d_in[2];
    const float* b_r = (const float*)d_in[3];
    const float* W_i = (const float*)d_in[4];
    const float* b_i = (const float*)d_in[5];
    const float* W_x = (const float*)d_in[6];
    float* out = (float*)d_out;

    float *pa, *pu;
    cudaGetSymbolAddress((void**)&pa, g_a);
    cudaGetSymbolAddress((void**)&pu, g_u);

    cudaFuncSetAttribute(gemm_f16, cudaFuncAttributeMaxDynamicSharedMemorySize, SMEM_H);
    cudaFuncSetAttribute(gemm_tf32<1>, cudaFuncAttributeMaxDynamicSharedMemorySize, SMEM_T);

    dim3 grid(DD / BN, MM / BM);   // (8, 128)
    gemm_f16<<<grid, 256, SMEM_H>>>(x, W_r, pa);
    gemm_f16<<<grid, 256, SMEM_H>>>(x, W_i, pu);
    gemm_tf32<1><<<grid, 256, SMEM_T>>>(x, W_x, nullptr, b_r, b_i);

    scan_pass1<<<(BD * CH) / 256, 256>>>();
    scan_pass2<<<BD / 256, 256>>>(h0, out + TOTL);
    scan_pass3<<<(BD * CH) / 256, 256>>>(out);
}

// round 7
// speedup vs baseline: 1.6571x; 1.3052x over previous
#include <cuda_runtime.h>
#include <cuda_fp16.h>
#include <cstdint>
#include <math.h>

// ---------------------------------------------------------------- constants
#define BB 4
#define TT 4096
#define DD 1024
#define MM (BB * TT)            // 16384
#define TOTL ((size_t)MM * DD)  // 16777216
#define BD (BB * DD)            // 4096
#define CH 64                   // scan chunks per sequence
#define CLEN (TT / CH)          // 64

#define LOG8F 2.0794415416798357f

// ---------------------------------------------------------------- scratch
__device__ float  g_a[MM * DD];     // raw zr -> a
__device__ float  g_u[MM * DD];     // raw zi -> u
__device__ __half g_xh[MM * DD];    // fp16 x
__device__ __half g_wh[3][DD * DD]; // fp16 Wr, Wi, Wx
__device__ float  g_P[BD * CH];
__device__ float  g_Q[BD * CH];
__device__ float  g_S[BD * CH];

// ---------------------------------------------------------------- utils
__device__ __forceinline__ void mma_f16(float* d, const uint32_t* a, const uint32_t* b) {
    asm volatile(
        "mma.sync.aligned.m16n8k16.row.col.f32.f16.f16.f32 "
        "{%0,%1,%2,%3}, {%4,%5,%6,%7}, {%8,%9}, {%0,%1,%2,%3};"
        : "+f"(d[0]), "+f"(d[1]), "+f"(d[2]), "+f"(d[3])
        : "r"(a[0]), "r"(a[1]), "r"(a[2]), "r"(a[3]), "r"(b[0]), "r"(b[1]));
}

// fp32 -> fp16 pre-conversion (vectorized: 4 floats per thread)
__global__ void __launch_bounds__(256)
cvt_half(const float* __restrict__ src, __half* __restrict__ dst) {
    const size_t i = (size_t)blockIdx.x * 256 + threadIdx.x;
    float4 v = ((const float4*)src)[i];
    half2 h01 = __floats2half2_rn(v.x, v.y);
    half2 h23 = __floats2half2_rn(v.z, v.w);
    ((uint2*)dst)[i] = make_uint2(*(uint32_t*)&h01, *(uint32_t*)&h23);
}

// ================================================================ fp16 GEMM
// C[m,n] = sum_k A[m,k]*W[n,k] (NT), fp16 in / fp32 accum.
// 128x128x32 CTA tile, 8 warps (2Mx4N), 64x32 warp tile, double-buffered.
// GATE=1: epilogue reads raw zr/zi from g_a/g_u, applies gate math with
// acc (= zx) and overwrites g_a/g_u with (a, u).
#define BM 128
#define BN 128
#define BK 32
#define NK (DD / BK)                   // 32
#define RSH 40                         // halves per smem row (32 + 8 pad)
#define HSTAGE (128 * RSH)             // halves per stage
#define SMEM_H (2 * 2 * HSTAGE * 2)    // 40960 bytes

template <int GATE>
__global__ void __launch_bounds__(256, 2)
gemm_f16(const __half* __restrict__ A, const __half* __restrict__ W,
         float* __restrict__ C,
         const float* __restrict__ br, const float* __restrict__ bi)
{
    extern __shared__ __half hsmem[];
    __half* As = hsmem;                  // [2][128][RSH]
    __half* Bs = hsmem + 2 * HSTAGE;

    const int tid = threadIdx.x;
    const int wid = tid >> 5;
    const int lane = tid & 31;
    const int r = lane >> 2;
    const int c = lane & 3;
    const int mw = (wid >> 2) * 64;
    const int nw = (wid & 3) * 32;
    const int bm = blockIdx.y * BM;
    const int bn = blockIdx.x * BN;

    float acc[4][4][4];
#pragma unroll
    for (int i = 0; i < 4; i++)
#pragma unroll
        for (int j = 0; j < 4; j++)
#pragma unroll
            for (int q = 0; q < 4; q++) acc[i][j][q] = 0.f;

    // tile load: u = tid + 256*i -> row = u>>2 (0..127), col8 = u&3 (8 halves)
#pragma unroll
    for (int i = 0; i < 2; i++) {
        const int u = tid + 256 * i;
        const int row = u >> 2, col8 = u & 3;
        *(int4*)&As[row * RSH + col8 * 8] =
            *(const int4*)(A + (size_t)(bm + row) * DD + col8 * 8);
        *(int4*)&Bs[row * RSH + col8 * 8] =
            *(const int4*)(W + (size_t)(bn + row) * DD + col8 * 8);
    }
    __syncthreads();

    for (int kt = 0; kt < NK; kt++) {
        const int s = kt & 1;
        if (kt + 1 < NK) {
            const int k0 = (kt + 1) * BK;
#pragma unroll
            for (int i = 0; i < 2; i++) {
                const int u = tid + 256 * i;
                const int row = u >> 2, col8 = u & 3;
                *(int4*)&As[(s ^ 1) * HSTAGE + row * RSH + col8 * 8] =
                    *(const int4*)(A + (size_t)(bm + row) * DD + k0 + col8 * 8);
                *(int4*)&Bs[(s ^ 1) * HSTAGE + row * RSH + col8 * 8] =
                    *(const int4*)(W + (size_t)(bn + row) * DD + k0 + col8 * 8);
            }
        }
        // two k16 steps cover BK=32
#pragma unroll
        for (int kk = 0; kk < BK; kk += 16) {
            uint32_t af[4][4], bf[4][2];
#pragma unroll
            for (int mi = 0; mi < 4; mi++) {
                const __half* pa = &As[s * HSTAGE + (mw + mi * 16 + r) * RSH + kk + 2 * c];
                af[mi][0] = *(const uint32_t*)(pa);
                af[mi][1] = *(const uint32_t*)(pa + 8 * RSH);
                af[mi][2] = *(const uint32_t*)(pa + 8);
                af[mi][3] = *(const uint32_t*)(pa + 8 * RSH + 8);
            }
#pragma unroll
            for (int ni = 0; ni < 4; ni++) {
                const __half* pb = &Bs[s * HSTAGE + (nw + ni * 8 + r) * RSH + kk + 2 * c];
                bf[ni][0] = *(const uint32_t*)(pb);
                bf[ni][1] = *(const uint32_t*)(pb + 8);
            }
#pragma unroll
            for (int mi = 0; mi < 4; mi++)
#pragma unroll
                for (int ni = 0; ni < 4; ni++)
                    mma_f16(acc[mi][ni], af[mi], bf[ni]);
        }
        __syncthreads();
    }

    // ---- epilogue
#pragma unroll
    for (int mi = 0; mi < 4; mi++) {
#pragma unroll
        for (int ni = 0; ni < 4; ni++) {
            const int m0 = bm + mw + mi * 16 + r;
            const int n  = bn + nw + ni * 8 + c * 2;
            if (GATE == 0) {
                *(float2*)(C + (size_t)m0 * DD + n) =
                    make_float2(acc[mi][ni][0], acc[mi][ni][1]);
                *(float2*)(C + (size_t)(m0 + 8) * DD + n) =
                    make_float2(acc[mi][ni][2], acc[mi][ni][3]);
            } else {
                const float br0 = __ldg(br + n), br1 = __ldg(br + n + 1);
                const float bi0 = __ldg(bi + n), bi1 = __ldg(bi + n + 1);
#pragma unroll
                for (int h = 0; h < 2; h++) {
                    const size_t idx = (size_t)(m0 + 8 * h) * DD + n;
                    float2 zr = *(float2*)&g_a[idx];
                    float2 zi = *(float2*)&g_u[idx];
                    float av[2], uv[2];
#pragma unroll
                    for (int q = 0; q < 2; q++) {
                        const float zrv = (q ? zr.y : zr.x) + (q ? br1 : br0);
                        const float ziv = (q ? zi.y : zi.x) + (q ? bi1 : bi0);
                        const float rr = 1.f / (1.f + __expf(-zrv));
                        // exp(-softplus(log8*r)) == sigmoid(-log8*r)
                        const float a = 1.f / (1.f + __expf(LOG8F * rr));
                        const float g = sqrtf(fmaxf(1.f - a * a, 1e-6f));
                        const float iv = 1.f / (1.f + __expf(-ziv));
                        av[q] = a;
                        uv[q] = g * iv * acc[mi][ni][h * 2 + q];
                    }
                    *(float2*)&g_a[idx] = make_float2(av[0], av[1]);
                    *(float2*)&g_u[idx] = make_float2(uv[0], uv[1]);
                }
            }
        }
    }
}

// ---------------------------------------------------------------- scan (3-pass)
__global__ void __launch_bounds__(256) scan_pass1() {
    const int g = blockIdx.x * 256 + threadIdx.x;
    const int d = g & (DD - 1);
    const int ch = (g >> 10) & (CH - 1);
    const int b = g >> 16;
    const size_t base = (size_t)b * TT * DD + (size_t)ch * CLEN * DD + d;
    float P = 1.f, Q = 0.f;
#pragma unroll 8
    for (int j = 0; j < CLEN; j++) {
        const float a = g_a[base + (size_t)j * DD];
        const float u = g_u[base + (size_t)j * DD];
        P *= a;
        Q = fmaf(a, Q, u);
    }
    g_P[g] = P;
    g_Q[g] = Q;
}

__global__ void __launch_bounds__(256) scan_pass2(const float* __restrict__ h0,
                                                  float* __restrict__ hlast) {
    const int bd = blockIdx.x * 256 + threadIdx.x;
    const int b = bd >> 10, d = bd & (DD - 1);
    float S = h0[bd];
#pragma unroll
    for (int ch = 0; ch < CH; ch++) {
        const int idx = ((b * CH + ch) << 10) | d;
        g_S[idx] = S;
        S = fmaf(g_P[idx], S, g_Q[idx]);
    }
    hlast[bd] = S;
}

__global__ void __launch_bounds__(256) scan_pass3(float* __restrict__ out) {
    const int g = blockIdx.x * 256 + threadIdx.x;
    const int d = g & (DD - 1);
    const int ch = (g >> 10) & (CH - 1);
    const int b = g >> 16;
    const size_t base = (size_t)b * TT * DD + (size_t)ch * CLEN * DD + d;
    float h = g_S[g];
#pragma unroll 8
    for (int j = 0; j < CLEN; j++) {
        h = fmaf(g_a[base + (size_t)j * DD], h, g_u[base + (size_t)j * DD]);
        out[base + (size_t)j * DD] = h;
    }
}

// ---------------------------------------------------------------- launch
extern "C" void kernel_launch(void* const* d_in, const int* in_sizes, int n_in,
                              void* d_out, int out_size)
{
    const float* x   = (const float*)d_in[0];
    const float* h0  = (const float*)d_in[1];
    const float* W_r = (const float*)d_in[2];
    const float* b_r = (const float*)d_in[3];
    const float* W_i = (const float*)d_in[4];
    const float* b_i = (const float*)d_in[5];
    const float* W_x = (const float*)d_in[6];
    float* out = (float*)d_out;

    float *pa, *pu;
    cudaGetSymbolAddress((void**)&pa, g_a);
    cudaGetSymbolAddress((void**)&pu, g_u);
    __half *xh, *wh;
    cudaGetSymbolAddress((void**)&xh, g_xh);
    cudaGetSymbolAddress((void**)&wh, g_wh);
    __half* wrh = wh;
    __half* wih = wh + (size_t)DD * DD;
    __half* wxh = wh + 2 * (size_t)DD * DD;

    cudaFuncSetAttribute(gemm_f16<0>, cudaFuncAttributeMaxDynamicSharedMemorySize, SMEM_H);
    cudaFuncSetAttribute(gemm_f16<1>, cudaFuncAttributeMaxDynamicSharedMemorySize, SMEM_H);

    // pre-convert inputs to fp16
    cvt_half<<<(int)(TOTL / 4 / 256), 256>>>(x, xh);
    cvt_half<<<(DD * DD / 4) / 256, 256>>>(W_r, wrh);
    cvt_half<<<(DD * DD / 4) / 256, 256>>>(W_i, wih);
    cvt_half<<<(DD * DD / 4) / 256, 256>>>(W_x, wxh);

    dim3 grid(DD / BN, MM / BM);   // (8, 128)
    gemm_f16<0><<<grid, 256, SMEM_H>>>(xh, wrh, pa, nullptr, nullptr);
    gemm_f16<0><<<grid, 256, SMEM_H>>>(xh, wih, pu, nullptr, nullptr);
    gemm_f16<1><<<grid, 256, SMEM_H>>>(xh, wxh, nullptr, b_r, b_i);

    scan_pass1<<<(BD * CH) / 256, 256>>>();
    scan_pass2<<<BD / 256, 256>>>(h0, out + TOTL);
    scan_pass3<<<(BD * CH) / 256, 256>>>(out);
}

// round 8
// speedup vs baseline: 1.9970x; 1.2052x over previous
#include <cuda_runtime.h>
#include <cuda_fp16.h>
#include <cstdint>
#include <math.h>

// ---------------------------------------------------------------- constants
#define BB 4
#define TT 4096
#define DD 1024
#define MM (BB * TT)            // 16384
#define TOTL ((size_t)MM * DD)  // 16777216
#define BD (BB * DD)            // 4096
#define CH 64                   // scan chunks per sequence
#define CLEN (TT / CH)          // 64

#define LOG8F 2.0794415416798357f

// ---------------------------------------------------------------- scratch
__device__ float  g_a[MM * DD];     // raw zr -> a
__device__ float  g_u[MM * DD];     // raw zi -> u
__device__ __half g_xh[MM * DD];    // fp16 x
__device__ __half g_wh[3][DD * DD]; // fp16 Wr, Wi, Wx
__device__ float  g_P[BD * CH];
__device__ float  g_Q[BD * CH];
__device__ float  g_S[BD * CH];

// ---------------------------------------------------------------- ptx utils
__device__ __forceinline__ uint32_t smem_u32(const void* p) {
    uint32_t a;
    asm("{ .reg .u64 t; cvta.to.shared.u64 t, %1; cvt.u32.u64 %0, t; }" : "=r"(a) : "l"(p));
    return a;
}
__device__ __forceinline__ void mma_f16(float* d, const uint32_t* a, const uint32_t* b) {
    asm volatile(
        "mma.sync.aligned.m16n8k16.row.col.f32.f16.f16.f32 "
        "{%0,%1,%2,%3}, {%4,%5,%6,%7}, {%8,%9}, {%0,%1,%2,%3};"
        : "+f"(d[0]), "+f"(d[1]), "+f"(d[2]), "+f"(d[3])
        : "r"(a[0]), "r"(a[1]), "r"(a[2]), "r"(a[3]), "r"(b[0]), "r"(b[1]));
}
__device__ __forceinline__ void ldsm_x4(uint32_t* r, uint32_t addr) {
    asm volatile("ldmatrix.sync.aligned.m8n8.x4.shared.b16 {%0,%1,%2,%3}, [%4];"
                 : "=r"(r[0]), "=r"(r[1]), "=r"(r[2]), "=r"(r[3]) : "r"(addr));
}
__device__ __forceinline__ void cp16(uint32_t saddr, const void* g) {
    asm volatile("cp.async.cg.shared.global [%0], [%1], 16;" :: "r"(saddr), "l"(g));
}
#define CP_COMMIT() asm volatile("cp.async.commit_group;" ::: "memory")
#define CP_WAIT1()  asm volatile("cp.async.wait_group 1;" ::: "memory")

// fp32 -> fp16 pre-conversion (4 floats / thread)
__global__ void __launch_bounds__(256)
cvt_half(const float* __restrict__ src, __half* __restrict__ dst) {
    const size_t i = (size_t)blockIdx.x * 256 + threadIdx.x;
    float4 v = ((const float4*)src)[i];
    half2 h01 = __floats2half2_rn(v.x, v.y);
    half2 h23 = __floats2half2_rn(v.z, v.w);
    ((uint2*)dst)[i] = make_uint2(*(uint32_t*)&h01, *(uint32_t*)&h23);
}
// convert 3 weight matrices in one launch (blocks [0,1024)->Wr etc.)
__global__ void __launch_bounds__(256)
cvt_w3(const float* __restrict__ wr, const float* __restrict__ wi,
       const float* __restrict__ wx, __half* __restrict__ dst) {
    const int grp = blockIdx.x >> 10;                 // 1024 blocks per matrix
    const size_t i = ((size_t)(blockIdx.x & 1023)) * 256 + threadIdx.x;
    const float* src = (grp == 0) ? wr : ((grp == 1) ? wi : wx);
    float4 v = ((const float4*)src)[i];
    half2 h01 = __floats2half2_rn(v.x, v.y);
    half2 h23 = __floats2half2_rn(v.z, v.w);
    ((uint2*)(dst + (size_t)grp * DD * DD))[i] = make_uint2(*(uint32_t*)&h01, *(uint32_t*)&h23);
}

// ================================================================ fp16 GEMM
// C[m,n] = sum_k A[m,k]*W[n,k] (NT), fp16 in / fp32 accum.
// 128x128x32 CTA tile, 8 warps (2Mx4N), 64x32 warp tile.
// cp.async 3-stage pipeline + ldmatrix fragment loads.
// GATE=1: epilogue reads raw zr/zi from g_a/g_u, applies gate, overwrites.
#define BM 128
#define BN 128
#define BK 32
#define NK (DD / BK)                   // 32
#define STG 3
#define RSH 40                         // halves per smem row (32 + 8 pad)
#define HSTAGE (128 * RSH)             // halves per stage (5120)
#define B_OFF (STG * HSTAGE)           // halves
#define SMEM_H (2 * STG * HSTAGE * 2)  // 61440 bytes

template <int GATE>
__global__ void __launch_bounds__(256, 2)
gemm_f16(const __half* __restrict__ A, const __half* __restrict__ W,
         float* __restrict__ C,
         const float* __restrict__ br, const float* __restrict__ bi)
{
    extern __shared__ __half hsmem[];
    const uint32_t sb = smem_u32(hsmem);

    const int tid = threadIdx.x;
    const int wid = tid >> 5;
    const int lane = tid & 31;
    const int r = lane >> 2;
    const int c = lane & 3;
    const int mw = (wid >> 2) * 64;
    const int nw = (wid & 3) * 32;
    const int bm = blockIdx.y * BM;
    const int bn = blockIdx.x * BN;

    // tile-load mapping: row = tid>>2 (+64), col8 = tid&3 (16B)
    const int lrow = tid >> 2;
    const int lc8  = (tid & 3) * 8;

    // ldmatrix lane addressing
    const int a_row = mw + (lane & 15);
    const int a_k8  = (lane >> 4) * 8;
    const int b_n   = nw + ((lane >> 4) << 3) + (lane & 7);
    const int b_k8  = ((lane >> 3) & 1) * 8;

    float acc[4][4][4];
#pragma unroll
    for (int i = 0; i < 4; i++)
#pragma unroll
        for (int j = 0; j < 4; j++)
#pragma unroll
            for (int q = 0; q < 4; q++) acc[i][j][q] = 0.f;

    // async tile loader: stage kt -> buffer kt%STG
    auto issue = [&](int kt) {
        const int s = kt % STG;
        const int k0 = kt * BK;
#pragma unroll
        for (int h = 0; h < 2; h++) {
            const int row = lrow + 64 * h;
            cp16(sb + 2 * (s * HSTAGE + row * RSH + lc8),
                 A + (size_t)(bm + row) * DD + k0 + lc8);
            cp16(sb + 2 * (B_OFF + s * HSTAGE + row * RSH + lc8),
                 W + (size_t)(bn + row) * DD + k0 + lc8);
        }
    };

    issue(0); CP_COMMIT();
    issue(1); CP_COMMIT();

    for (int kt = 0; kt < NK; kt++) {
        if (kt + 2 < NK) issue(kt + 2);
        CP_COMMIT();             // commit every iter (possibly empty) so wait1 == stage kt ready
        CP_WAIT1();
        __syncthreads();

        const int s = kt % STG;
        const uint32_t abase = sb + 2 * (s * HSTAGE + a_row * RSH + a_k8);
        const uint32_t bbase = sb + 2 * (B_OFF + s * HSTAGE + b_n * RSH + b_k8);
#pragma unroll
        for (int kk = 0; kk < BK; kk += 16) {
            uint32_t af[4][4], bf[4][2];
#pragma unroll
            for (int mi = 0; mi < 4; mi++)
                ldsm_x4(af[mi], abase + 2 * (mi * 16 * RSH + kk));
#pragma unroll
            for (int nj = 0; nj < 2; nj++) {
                uint32_t t[4];
                ldsm_x4(t, bbase + 2 * (nj * 16 * RSH + kk));
                bf[nj * 2][0] = t[0]; bf[nj * 2][1] = t[1];
                bf[nj * 2 + 1][0] = t[2]; bf[nj * 2 + 1][1] = t[3];
            }
#pragma unroll
            for (int mi = 0; mi < 4; mi++)
#pragma unroll
                for (int ni = 0; ni < 4; ni++)
                    mma_f16(acc[mi][ni], af[mi], bf[ni]);
        }
        __syncthreads();
    }

    // ---- epilogue
#pragma unroll
    for (int mi = 0; mi < 4; mi++) {
#pragma unroll
        for (int ni = 0; ni < 4; ni++) {
            const int m0 = bm + mw + mi * 16 + r;
            const int n  = bn + nw + ni * 8 + c * 2;
            if (GATE == 0) {
                *(float2*)(C + (size_t)m0 * DD + n) =
                    make_float2(acc[mi][ni][0], acc[mi][ni][1]);
                *(float2*)(C + (size_t)(m0 + 8) * DD + n) =
                    make_float2(acc[mi][ni][2], acc[mi][ni][3]);
            } else {
                const float br0 = __ldg(br + n), br1 = __ldg(br + n + 1);
                const float bi0 = __ldg(bi + n), bi1 = __ldg(bi + n + 1);
#pragma unroll
                for (int h = 0; h < 2; h++) {
                    const size_t idx = (size_t)(m0 + 8 * h) * DD + n;
                    float2 zr = *(float2*)&g_a[idx];
                    float2 zi = *(float2*)&g_u[idx];
                    float av[2], uv[2];
#pragma unroll
                    for (int q = 0; q < 2; q++) {
                        const float zrv = (q ? zr.y : zr.x) + (q ? br1 : br0);
                        const float ziv = (q ? zi.y : zi.x) + (q ? bi1 : bi0);
                        const float rr = 1.f / (1.f + __expf(-zrv));
                        // exp(-softplus(log8*r)) == sigmoid(-log8*r)
                        const float a = 1.f / (1.f + __expf(LOG8F * rr));
                        const float g = sqrtf(fmaxf(1.f - a * a, 1e-6f));
                        const float iv = 1.f / (1.f + __expf(-ziv));
                        av[q] = a;
                        uv[q] = g * iv * acc[mi][ni][h * 2 + q];
                    }
                    *(float2*)&g_a[idx] = make_float2(av[0], av[1]);
                    *(float2*)&g_u[idx] = make_float2(uv[0], uv[1]);
                }
            }
        }
    }
}

// ---------------------------------------------------------------- scan (3-pass)
__global__ void __launch_bounds__(256) scan_pass1() {
    const int g = blockIdx.x * 256 + threadIdx.x;
    const int d = g & (DD - 1);
    const int ch = (g >> 10) & (CH - 1);
    const int b = g >> 16;
    const size_t base = (size_t)b * TT * DD + (size_t)ch * CLEN * DD + d;
    float P = 1.f, Q = 0.f;
#pragma unroll 8
    for (int j = 0; j < CLEN; j++) {
        const float a = g_a[base + (size_t)j * DD];
        const float u = g_u[base + (size_t)j * DD];
        P *= a;
        Q = fmaf(a, Q, u);
    }
    g_P[g] = P;
    g_Q[g] = Q;
}

__global__ void __launch_bounds__(256) scan_pass2(const float* __restrict__ h0,
                                                  float* __restrict__ hlast) {
    const int bd = blockIdx.x * 256 + threadIdx.x;
    const int b = bd >> 10, d = bd & (DD - 1);
    float S = h0[bd];
#pragma unroll
    for (int ch = 0; ch < CH; ch++) {
        const int idx = ((b * CH + ch) << 10) | d;
        g_S[idx] = S;
        S = fmaf(g_P[idx], S, g_Q[idx]);
    }
    hlast[bd] = S;
}

__global__ void __launch_bounds__(256) scan_pass3(float* __restrict__ out) {
    const int g = blockIdx.x * 256 + threadIdx.x;
    const int d = g & (DD - 1);
    const int ch = (g >> 10) & (CH - 1);
    const int b = g >> 16;
    const size_t base = (size_t)b * TT * DD + (size_t)ch * CLEN * DD + d;
    float h = g_S[g];
#pragma unroll 8
    for (int j = 0; j < CLEN; j++) {
        h = fmaf(g_a[base + (size_t)j * DD], h, g_u[base + (size_t)j * DD]);
        out[base + (size_t)j * DD] = h;
    }
}

// ---------------------------------------------------------------- launch
extern "C" void kernel_launch(void* const* d_in, const int* in_sizes, int n_in,
                              void* d_out, int out_size)
{
    const float* x   = (const float*)d_in[0];
    const float* h0  = (const float*)d_in[1];
    const float* W_r = (const float*)d_in[2];
    const float* b_r = (const float*)d_in[3];
    const float* W_i = (const float*)d_in[4];
    const float* b_i = (const float*)d_in[5];
    const float* W_x = (const float*)d_in[6];
    float* out = (float*)d_out;

    float *pa, *pu;
    cudaGetSymbolAddress((void**)&pa, g_a);
    cudaGetSymbolAddress((void**)&pu, g_u);
    __half *xh, *wh;
    cudaGetSymbolAddress((void**)&xh, g_xh);
    cudaGetSymbolAddress((void**)&wh, g_wh);
    __half* wrh = wh;
    __half* wih = wh + (size_t)DD * DD;
    __half* wxh = wh + 2 * (size_t)DD * DD;

    cudaFuncSetAttribute(gemm_f16<0>, cudaFuncAttributeMaxDynamicSharedMemorySize, SMEM_H);
    cudaFuncSetAttribute(gemm_f16<1>, cudaFuncAttributeMaxDynamicSharedMemorySize, SMEM_H);

    cvt_half<<<(int)(TOTL / 4 / 256), 256>>>(x, xh);
    cvt_w3<<<3 * 1024, 256>>>(W_r, W_i, W_x, wh);

    dim3 grid(DD / BN, MM / BM);   // (8, 128)
    gemm_f16<0><<<grid, 256, SMEM_H>>>(xh, wrh, pa, nullptr, nullptr);
    gemm_f16<0><<<grid, 256, SMEM_H>>>(xh, wih, pu, nullptr, nullptr);
    gemm_f16<1><<<grid, 256, SMEM_H>>>(xh, wxh, nullptr, b_r, b_i);

    scan_pass1<<<(BD * CH) / 256, 256>>>();
    scan_pass2<<<BD / 256, 256>>>(h0, out + TOTL);
    scan_pass3<<<(BD * CH) / 256, 256>>>(out);
}

// round 9
// speedup vs baseline: 2.1651x; 1.0842x over previous
#include <cuda_runtime.h>
#include <cuda_fp16.h>
#include <cstdint>
#include <math.h>

// ---------------------------------------------------------------- constants
#define BB 4
#define TT 4096
#define DD 1024
#define MM (BB * TT)            // 16384
#define TOTL ((size_t)MM * DD)  // 16777216
#define BD (BB * DD)            // 4096
#define CH 64                   // scan chunks per sequence
#define CLEN (TT / CH)          // 64

#define LOG8F 2.0794415416798357f

// ---------------------------------------------------------------- scratch
__device__ float  g_a[MM * DD];     // raw zr -> a
__device__ float  g_u[MM * DD];     // raw zi -> u
__device__ __half g_xh[MM * DD];    // fp16 x
__device__ __half g_wh[3][DD * DD]; // fp16 Wr, Wi, Wx
__device__ float  g_P[BD * CH];
__device__ float  g_Q[BD * CH];
__device__ float  g_S[BD * CH];

// ---------------------------------------------------------------- ptx utils
__device__ __forceinline__ uint32_t smem_u32(const void* p) {
    uint32_t a;
    asm("{ .reg .u64 t; cvta.to.shared.u64 t, %1; cvt.u32.u64 %0, t; }" : "=r"(a) : "l"(p));
    return a;
}
__device__ __forceinline__ void mma_f16(float* d, const uint32_t* a, const uint32_t* b) {
    asm volatile(
        "mma.sync.aligned.m16n8k16.row.col.f32.f16.f16.f32 "
        "{%0,%1,%2,%3}, {%4,%5,%6,%7}, {%8,%9}, {%0,%1,%2,%3};"
        : "+f"(d[0]), "+f"(d[1]), "+f"(d[2]), "+f"(d[3])
        : "r"(a[0]), "r"(a[1]), "r"(a[2]), "r"(a[3]), "r"(b[0]), "r"(b[1]));
}
__device__ __forceinline__ void ldsm_x4(uint32_t* r, uint32_t addr) {
    asm volatile("ldmatrix.sync.aligned.m8n8.x4.shared.b16 {%0,%1,%2,%3}, [%4];"
                 : "=r"(r[0]), "=r"(r[1]), "=r"(r[2]), "=r"(r[3]) : "r"(addr));
}
__device__ __forceinline__ void cp16(uint32_t saddr, const void* g) {
    asm volatile("cp.async.cg.shared.global [%0], [%1], 16;" :: "r"(saddr), "l"(g));
}
#define CP_COMMIT() asm volatile("cp.async.commit_group;" ::: "memory")
#define CP_WAIT2()  asm volatile("cp.async.wait_group 2;" ::: "memory")

// fp32 -> fp16 pre-conversion (4 floats / thread)
__global__ void __launch_bounds__(256)
cvt_half(const float* __restrict__ src, __half* __restrict__ dst) {
    const size_t i = (size_t)blockIdx.x * 256 + threadIdx.x;
    float4 v = ((const float4*)src)[i];
    half2 h01 = __floats2half2_rn(v.x, v.y);
    half2 h23 = __floats2half2_rn(v.z, v.w);
    ((uint2*)dst)[i] = make_uint2(*(uint32_t*)&h01, *(uint32_t*)&h23);
}
// convert 3 weight matrices in one launch
__global__ void __launch_bounds__(256)
cvt_w3(const float* __restrict__ wr, const float* __restrict__ wi,
       const float* __restrict__ wx, __half* __restrict__ dst) {
    const int grp = blockIdx.x >> 10;
    const size_t i = ((size_t)(blockIdx.x & 1023)) * 256 + threadIdx.x;
    const float* src = (grp == 0) ? wr : ((grp == 1) ? wi : wx);
    float4 v = ((const float4*)src)[i];
    half2 h01 = __floats2half2_rn(v.x, v.y);
    half2 h23 = __floats2half2_rn(v.z, v.w);
    ((uint2*)(dst + (size_t)grp * DD * DD))[i] = make_uint2(*(uint32_t*)&h01, *(uint32_t*)&h23);
}

// ================================================================ fp16 GEMM
// C[m,n] = sum_k A[m,k]*W[n,k] (NT), fp16 in / fp32 accum.
// 128x128x32 CTA tile, 8 warps (2Mx4N), 64x32 warp tile.
// 4-stage cp.async pipeline, ONE __syncthreads per k-tile, ldmatrix frags.
// GATE=1: epilogue reads raw zr/zi from g_a/g_u, applies gate, overwrites.
#define BM 128
#define BN 128
#define BK 32
#define NK (DD / BK)                   // 32
#define STG 4
#define RSH 40                         // halves per smem row (32 + 8 pad)
#define HSTAGE (128 * RSH)             // halves per stage (5120)
#define B_OFF (STG * HSTAGE)           // halves
#define SMEM_H (2 * STG * HSTAGE * 2)  // 81920 bytes

template <int GATE>
__global__ void __launch_bounds__(256, 2)
gemm_f16(const __half* __restrict__ A, const __half* __restrict__ W,
         float* __restrict__ C,
         const float* __restrict__ br, const float* __restrict__ bi)
{
    extern __shared__ __half hsmem[];
    const uint32_t sb = smem_u32(hsmem);

    const int tid = threadIdx.x;
    const int wid = tid >> 5;
    const int lane = tid & 31;
    const int r = lane >> 2;
    const int c = lane & 3;
    const int mw = (wid >> 2) * 64;
    const int nw = (wid & 3) * 32;
    const int bm = blockIdx.y * BM;
    const int bn = blockIdx.x * BN;

    // tile-load mapping: row = tid>>2 (+64), col8 = (tid&3)*8 halves (16B)
    const int lrow = tid >> 2;
    const int lc8  = (tid & 3) * 8;

    // ldmatrix lane addressing
    const int a_row = mw + (lane & 15);
    const int a_k8  = (lane >> 4) * 8;
    const int b_n   = nw + ((lane >> 4) << 3) + (lane & 7);
    const int b_k8  = ((lane >> 3) & 1) * 8;

    float acc[4][4][4];
#pragma unroll
    for (int i = 0; i < 4; i++)
#pragma unroll
        for (int j = 0; j < 4; j++)
#pragma unroll
            for (int q = 0; q < 4; q++) acc[i][j][q] = 0.f;

    auto issue = [&](int kt) {
        const int s = kt & (STG - 1);
        const int k0 = kt * BK;
#pragma unroll
        for (int h = 0; h < 2; h++) {
            const int row = lrow + 64 * h;
            cp16(sb + 2 * (s * HSTAGE + row * RSH + lc8),
                 A + (size_t)(bm + row) * DD + k0 + lc8);
            cp16(sb + 2 * (B_OFF + s * HSTAGE + row * RSH + lc8),
                 W + (size_t)(bn + row) * DD + k0 + lc8);
        }
    };

    issue(0); CP_COMMIT();
    issue(1); CP_COMMIT();
    issue(2); CP_COMMIT();

    for (int kt = 0; kt < NK; kt++) {
        CP_WAIT2();          // stage kt resident (<=2 younger groups pending)
        __syncthreads();     // writers of stage kt visible to all; buffer
                             // (kt-1)%4 fully consumed by all warps
        if (kt + 3 < NK) issue(kt + 3);
        CP_COMMIT();         // commit every iter (possibly empty) to keep count

        const int s = kt & (STG - 1);
        const uint32_t abase = sb + 2 * (s * HSTAGE + a_row * RSH + a_k8);
        const uint32_t bbase = sb + 2 * (B_OFF + s * HSTAGE + b_n * RSH + b_k8);
#pragma unroll
        for (int kk = 0; kk < BK; kk += 16) {
            uint32_t af[4][4], bf[4][2];
#pragma unroll
            for (int mi = 0; mi < 4; mi++)
                ldsm_x4(af[mi], abase + 2 * (mi * 16 * RSH + kk));
#pragma unroll
            for (int nj = 0; nj < 2; nj++) {
                uint32_t t[4];
                ldsm_x4(t, bbase + 2 * (nj * 16 * RSH + kk));
                bf[nj * 2][0] = t[0]; bf[nj * 2][1] = t[1];
                bf[nj * 2 + 1][0] = t[2]; bf[nj * 2 + 1][1] = t[3];
            }
#pragma unroll
            for (int mi = 0; mi < 4; mi++)
#pragma unroll
                for (int ni = 0; ni < 4; ni++)
                    mma_f16(acc[mi][ni], af[mi], bf[ni]);
        }
        // no trailing barrier: next iteration's top barrier protects reuse
    }

    // ---- epilogue
#pragma unroll
    for (int mi = 0; mi < 4; mi++) {
#pragma unroll
        for (int ni = 0; ni < 4; ni++) {
            const int m0 = bm + mw + mi * 16 + r;
            const int n  = bn + nw + ni * 8 + c * 2;
            if (GATE == 0) {
                *(float2*)(C + (size_t)m0 * DD + n) =
                    make_float2(acc[mi][ni][0], acc[mi][ni][1]);
                *(float2*)(C + (size_t)(m0 + 8) * DD + n) =
                    make_float2(acc[mi][ni][2], acc[mi][ni][3]);
            } else {
                const float br0 = __ldg(br + n), br1 = __ldg(br + n + 1);
                const float bi0 = __ldg(bi + n), bi1 = __ldg(bi + n + 1);
#pragma unroll
                for (int h = 0; h < 2; h++) {
                    const size_t idx = (size_t)(m0 + 8 * h) * DD + n;
                    float2 zr = *(float2*)&g_a[idx];
                    float2 zi = *(float2*)&g_u[idx];
                    float av[2], uv[2];
#pragma unroll
                    for (int q = 0; q < 2; q++) {
                        const float zrv = (q ? zr.y : zr.x) + (q ? br1 : br0);
                        const float ziv = (q ? zi.y : zi.x) + (q ? bi1 : bi0);
                        const float rr = 1.f / (1.f + __expf(-zrv));
                        // exp(-softplus(log8*r)) == sigmoid(-log8*r)
                        const float a = 1.f / (1.f + __expf(LOG8F * rr));
                        const float g = sqrtf(fmaxf(1.f - a * a, 1e-6f));
                        const float iv = 1.f / (1.f + __expf(-ziv));
                        av[q] = a;
                        uv[q] = g * iv * acc[mi][ni][h * 2 + q];
                    }
                    *(float2*)&g_a[idx] = make_float2(av[0], av[1]);
                    *(float2*)&g_u[idx] = make_float2(uv[0], uv[1]);
                }
            }
        }
    }
}

// ---------------------------------------------------------------- scan (3-pass)
__global__ void __launch_bounds__(256) scan_pass1() {
    const int g = blockIdx.x * 256 + threadIdx.x;
    const int d = g & (DD - 1);
    const int ch = (g >> 10) & (CH - 1);
    const int b = g >> 16;
    const size_t base = (size_t)b * TT * DD + (size_t)ch * CLEN * DD + d;
    float P = 1.f, Q = 0.f;
#pragma unroll 8
    for (int j = 0; j < CLEN; j++) {
        const float a = g_a[base + (size_t)j * DD];
        const float u = g_u[base + (size_t)j * DD];
        P *= a;
        Q = fmaf(a, Q, u);
    }
    g_P[g] = P;
    g_Q[g] = Q;
}

__global__ void __launch_bounds__(256) scan_pass2(const float* __restrict__ h0,
                                                  float* __restrict__ hlast) {
    const int bd = blockIdx.x * 256 + threadIdx.x;
    const int b = bd >> 10, d = bd & (DD - 1);
    float S = h0[bd];
#pragma unroll
    for (int ch = 0; ch < CH; ch++) {
        const int idx = ((b * CH + ch) << 10) | d;
        g_S[idx] = S;
        S = fmaf(g_P[idx], S, g_Q[idx]);
    }
    hlast[bd] = S;
}

__global__ void __launch_bounds__(256) scan_pass3(float* __restrict__ out) {
    const int g = blockIdx.x * 256 + threadIdx.x;
    const int d = g & (DD - 1);
    const int ch = (g >> 10) & (CH - 1);
    const int b = g >> 16;
    const size_t base = (size_t)b * TT * DD + (size_t)ch * CLEN * DD + d;
    float h = g_S[g];
#pragma unroll 8
    for (int j = 0; j < CLEN; j++) {
        h = fmaf(g_a[base + (size_t)j * DD], h, g_u[base + (size_t)j * DD]);
        out[base + (size_t)j * DD] = h;
    }
}

// ---------------------------------------------------------------- launch
extern "C" void kernel_launch(void* const* d_in, const int* in_sizes, int n_in,
                              void* d_out, int out_size)
{
    const float* x   = (const float*)d_in[0];
    const float* h0  = (const float*)d_in[1];
    const float* W_r = (const float*)d_in[2];
    const float* b_r = (const float*)d_in[3];
    const float* W_i = (const float*)d_in[4];
    const float* b_i = (const float*)d_in[5];
    const float* W_x = (const float*)d_in[6];
    float* out = (float*)d_out;

    float *pa, *pu;
    cudaGetSymbolAddress((void**)&pa, g_a);
    cudaGetSymbolAddress((void**)&pu, g_u);
    __half *xh, *wh;
    cudaGetSymbolAddress((void**)&xh, g_xh);
    cudaGetSymbolAddress((void**)&wh, g_wh);
    __half* wrh = wh;
    __half* wih = wh + (size_t)DD * DD;
    __half* wxh = wh + 2 * (size_t)DD * DD;

    cudaFuncSetAttribute(gemm_f16<0>, cudaFuncAttributeMaxDynamicSharedMemorySize, SMEM_H);
    cudaFuncSetAttribute(gemm_f16<1>, cudaFuncAttributeMaxDynamicSharedMemorySize, SMEM_H);

    cvt_half<<<(int)(TOTL / 4 / 256), 256>>>(x, xh);
    cvt_w3<<<3 * 1024, 256>>>(W_r, W_i, W_x, wh);

    dim3 grid(DD / BN, MM / BM);   // (8, 128)
    gemm_f16<0><<<grid, 256, SMEM_H>>>(xh, wrh, pa, nullptr, nullptr);
    gemm_f16<0><<<grid, 256, SMEM_H>>>(xh, wih, pu, nullptr, nullptr);
    gemm_f16<1><<<grid, 256, SMEM_H>>>(xh, wxh, nullptr, b_r, b_i);

    scan_pass1<<<(BD * CH) / 256, 256>>>();
    scan_pass2<<<BD / 256, 256>>>(h0, out + TOTL);
    scan_pass3<<<(BD * CH) / 256, 256>>>(out);
}

// round 10
// speedup vs baseline: 2.2100x; 1.0208x over previous
#include <cuda_runtime.h>
#include <cuda_fp16.h>
#include <cstdint>
#include <math.h>

// ---------------------------------------------------------------- constants
#define BB 4
#define TT 4096
#define DD 1024
#define MM (BB * TT)            // 16384
#define TOTL ((size_t)MM * DD)  // 16777216
#define BD (BB * DD)            // 4096
#define CH 64                   // scan chunks per sequence
#define CLEN (TT / CH)          // 64

#define LOG8F 2.0794415416798357f

// ---------------------------------------------------------------- scratch
__device__ float  g_a[MM * DD];     // raw zr -> a
__device__ float  g_u[MM * DD];     // raw zi -> u
__device__ __half g_xh[MM * DD];    // fp16 x
__device__ __half g_wh[3][DD * DD]; // fp16 Wr, Wi, Wx
__device__ float  g_P[BD * CH];
__device__ float  g_Q[BD * CH];
__device__ float  g_S[BD * CH];

// ---------------------------------------------------------------- ptx utils
__device__ __forceinline__ uint32_t smem_u32(const void* p) {
    uint32_t a;
    asm("{ .reg .u64 t; cvta.to.shared.u64 t, %1; cvt.u32.u64 %0, t; }" : "=r"(a) : "l"(p));
    return a;
}
__device__ __forceinline__ void mma_f16(float* d, const uint32_t* a, const uint32_t* b) {
    asm volatile(
        "mma.sync.aligned.m16n8k16.row.col.f32.f16.f16.f32 "
        "{%0,%1,%2,%3}, {%4,%5,%6,%7}, {%8,%9}, {%0,%1,%2,%3};"
        : "+f"(d[0]), "+f"(d[1]), "+f"(d[2]), "+f"(d[3])
        : "r"(a[0]), "r"(a[1]), "r"(a[2]), "r"(a[3]), "r"(b[0]), "r"(b[1]));
}
__device__ __forceinline__ void ldsm_x4(uint32_t* r, uint32_t addr) {
    asm volatile("ldmatrix.sync.aligned.m8n8.x4.shared.b16 {%0,%1,%2,%3}, [%4];"
                 : "=r"(r[0]), "=r"(r[1]), "=r"(r[2]), "=r"(r[3]) : "r"(addr));
}
__device__ __forceinline__ void cp16(uint32_t saddr, const void* g) {
    asm volatile("cp.async.cg.shared.global [%0], [%1], 16;" :: "r"(saddr), "l"(g));
}
#define CP_COMMIT() asm volatile("cp.async.commit_group;" ::: "memory")
#define CP_WAIT1()  asm volatile("cp.async.wait_group 1;" ::: "memory")

// fp32 -> fp16 pre-conversion (4 floats / thread)
__global__ void __launch_bounds__(256)
cvt_half(const float* __restrict__ src, __half* __restrict__ dst) {
    const size_t i = (size_t)blockIdx.x * 256 + threadIdx.x;
    float4 v = ((const float4*)src)[i];
    half2 h01 = __floats2half2_rn(v.x, v.y);
    half2 h23 = __floats2half2_rn(v.z, v.w);
    ((uint2*)dst)[i] = make_uint2(*(uint32_t*)&h01, *(uint32_t*)&h23);
}
// convert 3 weight matrices in one launch
__global__ void __launch_bounds__(256)
cvt_w3(const float* __restrict__ wr, const float* __restrict__ wi,
       const float* __restrict__ wx, __half* __restrict__ dst) {
    const int grp = blockIdx.x >> 10;
    const size_t i = ((size_t)(blockIdx.x & 1023)) * 256 + threadIdx.x;
    const float* src = (grp == 0) ? wr : ((grp == 1) ? wi : wx);
    float4 v = ((const float4*)src)[i];
    half2 h01 = __floats2half2_rn(v.x, v.y);
    half2 h23 = __floats2half2_rn(v.z, v.w);
    ((uint2*)(dst + (size_t)grp * DD * DD))[i] = make_uint2(*(uint32_t*)&h01, *(uint32_t*)&h23);
}

// ================================================================ fp16 GEMM
// C[m,n] = sum_k A[m,k]*W[n,k] (NT), fp16 in / fp32 accum.
// 128x128x64 CTA tile, 8 warps (2Mx4N), 64x32 warp tile.
// 3-stage cp.async pipeline, ONE __syncthreads per 64-wide k-tile, ldmatrix.
// GATE=1: epilogue reads raw zr/zi from g_a/g_u, applies gate, overwrites.
#define BM 128
#define BN 128
#define BK 64
#define NK (DD / BK)                   // 16
#define STG 3
#define RSH 72                         // halves per smem row (64 + 8 pad)
#define HSTAGE (128 * RSH)             // halves per stage (9216)
#define B_OFF (STG * HSTAGE)           // halves
#define SMEM_H (2 * STG * HSTAGE * 2)  // 110592 bytes

template <int GATE>
__global__ void __launch_bounds__(256, 2)
gemm_f16(const __half* __restrict__ A, const __half* __restrict__ W,
         float* __restrict__ C,
         const float* __restrict__ br, const float* __restrict__ bi)
{
    extern __shared__ __half hsmem[];
    const uint32_t sb = smem_u32(hsmem);

    const int tid = threadIdx.x;
    const int wid = tid >> 5;
    const int lane = tid & 31;
    const int r = lane >> 2;
    const int c = lane & 3;
    const int mw = (wid >> 2) * 64;
    const int nw = (wid & 3) * 32;
    const int bm = blockIdx.y * BM;
    const int bn = blockIdx.x * BN;

    // tile-load mapping: u = tid + 256*i -> row = u>>3 (0..127), col8 = (u&7)*8
    // ldmatrix lane addressing
    const int a_row = mw + (lane & 15);
    const int a_k8  = (lane >> 4) * 8;
    const int b_n   = nw + ((lane >> 4) << 3) + (lane & 7);
    const int b_k8  = ((lane >> 3) & 1) * 8;

    float acc[4][4][4];
#pragma unroll
    for (int i = 0; i < 4; i++)
#pragma unroll
        for (int j = 0; j < 4; j++)
#pragma unroll
            for (int q = 0; q < 4; q++) acc[i][j][q] = 0.f;

    auto issue = [&](int kt) {
        const int s = kt % STG;
        const int k0 = kt * BK;
#pragma unroll
        for (int i = 0; i < 4; i++) {
            const int u = tid + 256 * i;
            const int row = u >> 3, c8 = (u & 7) * 8;
            cp16(sb + 2 * (s * HSTAGE + row * RSH + c8),
                 A + (size_t)(bm + row) * DD + k0 + c8);
            cp16(sb + 2 * (B_OFF + s * HSTAGE + row * RSH + c8),
                 W + (size_t)(bn + row) * DD + k0 + c8);
        }
    };

    issue(0); CP_COMMIT();
    issue(1); CP_COMMIT();

    for (int kt = 0; kt < NK; kt++) {
        CP_WAIT1();          // stage kt resident (<=1 younger group pending)
        __syncthreads();     // stage-kt writes visible; buffer (kt-1)%3 free
        if (kt + 2 < NK) issue(kt + 2);
        CP_COMMIT();         // commit every iter (possibly empty) to keep count

        const int s = kt % STG;
        const uint32_t abase = sb + 2 * (s * HSTAGE + a_row * RSH + a_k8);
        const uint32_t bbase = sb + 2 * (B_OFF + s * HSTAGE + b_n * RSH + b_k8);
#pragma unroll
        for (int kk = 0; kk < BK; kk += 16) {
            uint32_t af[4][4], bf[4][2];
#pragma unroll
            for (int mi = 0; mi < 4; mi++)
                ldsm_x4(af[mi], abase + 2 * (mi * 16 * RSH + kk));
#pragma unroll
            for (int nj = 0; nj < 2; nj++) {
                uint32_t t[4];
                ldsm_x4(t, bbase + 2 * (nj * 16 * RSH + kk));
                bf[nj * 2][0] = t[0]; bf[nj * 2][1] = t[1];
                bf[nj * 2 + 1][0] = t[2]; bf[nj * 2 + 1][1] = t[3];
            }
#pragma unroll
            for (int mi = 0; mi < 4; mi++)
#pragma unroll
                for (int ni = 0; ni < 4; ni++)
                    mma_f16(acc[mi][ni], af[mi], bf[ni]);
        }
        // no trailing barrier: next iteration's top barrier protects reuse
    }

    // ---- epilogue
#pragma unroll
    for (int mi = 0; mi < 4; mi++) {
#pragma unroll
        for (int ni = 0; ni < 4; ni++) {
            const int m0 = bm + mw + mi * 16 + r;
            const int n  = bn + nw + ni * 8 + c * 2;
            if (GATE == 0) {
                *(float2*)(C + (size_t)m0 * DD + n) =
                    make_float2(acc[mi][ni][0], acc[mi][ni][1]);
                *(float2*)(C + (size_t)(m0 + 8) * DD + n) =
                    make_float2(acc[mi][ni][2], acc[mi][ni][3]);
            } else {
                const float br0 = __ldg(br + n), br1 = __ldg(br + n + 1);
                const float bi0 = __ldg(bi + n), bi1 = __ldg(bi + n + 1);
#pragma unroll
                for (int h = 0; h < 2; h++) {
                    const size_t idx = (size_t)(m0 + 8 * h) * DD + n;
                    float2 zr = *(float2*)&g_a[idx];
                    float2 zi = *(float2*)&g_u[idx];
                    float av[2], uv[2];
#pragma unroll
                    for (int q = 0; q < 2; q++) {
                        const float zrv = (q ? zr.y : zr.x) + (q ? br1 : br0);
                        const float ziv = (q ? zi.y : zi.x) + (q ? bi1 : bi0);
                        const float rr = 1.f / (1.f + __expf(-zrv));
                        // exp(-softplus(log8*r)) == sigmoid(-log8*r)
                        const float a = 1.f / (1.f + __expf(LOG8F * rr));
                        const float g = sqrtf(fmaxf(1.f - a * a, 1e-6f));
                        const float iv = 1.f / (1.f + __expf(-ziv));
                        av[q] = a;
                        uv[q] = g * iv * acc[mi][ni][h * 2 + q];
                    }
                    *(float2*)&g_a[idx] = make_float2(av[0], av[1]);
                    *(float2*)&g_u[idx] = make_float2(uv[0], uv[1]);
                }
            }
        }
    }
}

// ---------------------------------------------------------------- scan (3-pass)
__global__ void __launch_bounds__(256) scan_pass1() {
    const int g = blockIdx.x * 256 + threadIdx.x;
    const int d = g & (DD - 1);
    const int ch = (g >> 10) & (CH - 1);
    const int b = g >> 16;
    const size_t base = (size_t)b * TT * DD + (size_t)ch * CLEN * DD + d;
    float P = 1.f, Q = 0.f;
#pragma unroll 8
    for (int j = 0; j < CLEN; j++) {
        const float a = g_a[base + (size_t)j * DD];
        const float u = g_u[base + (size_t)j * DD];
        P *= a;
        Q = fmaf(a, Q, u);
    }
    g_P[g] = P;
    g_Q[g] = Q;
}

__global__ void __launch_bounds__(256) scan_pass2(const float* __restrict__ h0,
                                                  float* __restrict__ hlast) {
    const int bd = blockIdx.x * 256 + threadIdx.x;
    const int b = bd >> 10, d = bd & (DD - 1);
    float S = h0[bd];
#pragma unroll
    for (int ch = 0; ch < CH; ch++) {
        const int idx = ((b * CH + ch) << 10) | d;
        g_S[idx] = S;
        S = fmaf(g_P[idx], S, g_Q[idx]);
    }
    hlast[bd] = S;
}

__global__ void __launch_bounds__(256) scan_pass3(float* __restrict__ out) {
    const int g = blockIdx.x * 256 + threadIdx.x;
    const int d = g & (DD - 1);
    const int ch = (g >> 10) & (CH - 1);
    const int b = g >> 16;
    const size_t base = (size_t)b * TT * DD + (size_t)ch * CLEN * DD + d;
    float h = g_S[g];
#pragma unroll 8
    for (int j = 0; j < CLEN; j++) {
        h = fmaf(g_a[base + (size_t)j * DD], h, g_u[base + (size_t)j * DD]);
        out[base + (size_t)j * DD] = h;
    }
}

// ---------------------------------------------------------------- launch
extern "C" void kernel_launch(void* const* d_in, const int* in_sizes, int n_in,
                              void* d_out, int out_size)
{
    const float* x   = (const float*)d_in[0];
    const float* h0  = (const float*)d_in[1];
    const float* W_r = (const float*)d_in[2];
    const float* b_r = (const float*)d_in[3];
    const float* W_i = (const float*)d_in[4];
    const float* b_i = (const float*)d_in[5];
    const float* W_x = (const float*)d_in[6];
    float* out = (float*)d_out;

    float *pa, *pu;
    cudaGetSymbolAddress((void**)&pa, g_a);
    cudaGetSymbolAddress((void**)&pu, g_u);
    __half *xh, *wh;
    cudaGetSymbolAddress((void**)&xh, g_xh);
    cudaGetSymbolAddress((void**)&wh, g_wh);
    __half* wrh = wh;
    __half* wih = wh + (size_t)DD * DD;
    __half* wxh = wh + 2 * (size_t)DD * DD;

    cudaFuncSetAttribute(gemm_f16<0>, cudaFuncAttributeMaxDynamicSharedMemorySize, SMEM_H);
    cudaFuncSetAttribute(gemm_f16<1>, cudaFuncAttributeMaxDynamicSharedMemorySize, SMEM_H);

    cvt_half<<<(int)(TOTL / 4 / 256), 256>>>(x, xh);
    cvt_w3<<<3 * 1024, 256>>>(W_r, W_i, W_x, wh);

    dim3 grid(DD / BN, MM / BM);   // (8, 128)
    gemm_f16<0><<<grid, 256, SMEM_H>>>(xh, wrh, pa, nullptr, nullptr);
    gemm_f16<0><<<grid, 256, SMEM_H>>>(xh, wih, pu, nullptr, nullptr);
    gemm_f16<1><<<grid, 256, SMEM_H>>>(xh, wxh, nullptr, b_r, b_i);

    scan_pass1<<<(BD * CH) / 256, 256>>>();
    scan_pass2<<<BD / 256, 256>>>(h0, out + TOTL);
    scan_pass3<<<(BD * CH) / 256, 256>>>(out);
}

// round 11
// speedup vs baseline: 2.3542x; 1.0652x over previous
#include <cuda_runtime.h>
#include <cuda_fp16.h>
#include <cstdint>
#include <math.h>

// ---------------------------------------------------------------- constants
#define BB 4
#define TT 4096
#define DD 1024
#define MM (BB * TT)            // 16384
#define TOTL ((size_t)MM * DD)  // 16777216
#define BD (BB * DD)            // 4096
#define CH 64                   // scan chunks per sequence
#define CLEN (TT / CH)          // 64

#define LOG8F 2.0794415416798357f

// ---------------------------------------------------------------- scratch
__device__ float  g_a[MM * DD];     // decay a (fp32, scan input)
__device__ float  g_u[MM * DD];     // input term u (fp32, scan input)
__device__ __half g_zr[MM * DD];    // fp16 raw zr
__device__ __half g_zi[MM * DD];    // fp16 raw zi
__device__ __half g_xh[MM * DD];    // fp16 x
__device__ __half g_wh[3][DD * DD]; // fp16 Wr, Wi, Wx
__device__ float  g_P[BD * CH];
__device__ float  g_Q[BD * CH];
__device__ float  g_S[BD * CH];

// ---------------------------------------------------------------- ptx utils
__device__ __forceinline__ uint32_t smem_u32(const void* p) {
    uint32_t a;
    asm("{ .reg .u64 t; cvta.to.shared.u64 t, %1; cvt.u32.u64 %0, t; }" : "=r"(a) : "l"(p));
    return a;
}
__device__ __forceinline__ void mma_f16(float* d, const uint32_t* a, const uint32_t* b) {
    asm volatile(
        "mma.sync.aligned.m16n8k16.row.col.f32.f16.f16.f32 "
        "{%0,%1,%2,%3}, {%4,%5,%6,%7}, {%8,%9}, {%0,%1,%2,%3};"
        : "+f"(d[0]), "+f"(d[1]), "+f"(d[2]), "+f"(d[3])
        : "r"(a[0]), "r"(a[1]), "r"(a[2]), "r"(a[3]), "r"(b[0]), "r"(b[1]));
}
__device__ __forceinline__ void ldsm_x4(uint32_t* r, uint32_t addr) {
    asm volatile("ldmatrix.sync.aligned.m8n8.x4.shared.b16 {%0,%1,%2,%3}, [%4];"
                 : "=r"(r[0]), "=r"(r[1]), "=r"(r[2]), "=r"(r[3]) : "r"(addr));
}
__device__ __forceinline__ void cp16(uint32_t saddr, const void* g) {
    asm volatile("cp.async.cg.shared.global [%0], [%1], 16;" :: "r"(saddr), "l"(g));
}
#define CP_COMMIT() asm volatile("cp.async.commit_group;" ::: "memory")
#define CP_WAIT1()  asm volatile("cp.async.wait_group 1;" ::: "memory")

// fp32 -> fp16 pre-conversion (4 floats / thread)
__global__ void __launch_bounds__(256)
cvt_half(const float* __restrict__ src, __half* __restrict__ dst) {
    const size_t i = (size_t)blockIdx.x * 256 + threadIdx.x;
    float4 v = ((const float4*)src)[i];
    half2 h01 = __floats2half2_rn(v.x, v.y);
    half2 h23 = __floats2half2_rn(v.z, v.w);
    ((uint2*)dst)[i] = make_uint2(*(uint32_t*)&h01, *(uint32_t*)&h23);
}
__global__ void __launch_bounds__(256)
cvt_w3(const float* __restrict__ wr, const float* __restrict__ wi,
       const float* __restrict__ wx, __half* __restrict__ dst) {
    const int grp = blockIdx.x >> 10;
    const size_t i = ((size_t)(blockIdx.x & 1023)) * 256 + threadIdx.x;
    const float* src = (grp == 0) ? wr : ((grp == 1) ? wi : wx);
    float4 v = ((const float4*)src)[i];
    half2 h01 = __floats2half2_rn(v.x, v.y);
    half2 h23 = __floats2half2_rn(v.z, v.w);
    ((uint2*)(dst + (size_t)grp * DD * DD))[i] = make_uint2(*(uint32_t*)&h01, *(uint32_t*)&h23);
}

// ================================================================ fp16 GEMM
// C[m,n] = sum_k A[m,k]*W[n,k] (NT), fp16 in / fp32 accum.
// 128x128x64 CTA tile, 8 warps (2Mx4N), 64x32 warp tile.
// 3-stage cp.async pipeline, one __syncthreads per k-tile, ldmatrix frags.
#define BM 128
#define BN 128
#define BK 64
#define NK (DD / BK)                   // 16
#define STG 3
#define RSH 72                         // halves per smem row (64 + 8 pad)
#define HSTAGE (128 * RSH)             // halves per stage (9216)
#define B_OFF (STG * HSTAGE)           // halves
#define SMEM_H (2 * STG * HSTAGE * 2)  // 110592 bytes

// shared mainloop body: computes 128x128 fp32 acc for (A, W) tile
#define GEMM_MAINLOOP(A_, W_)                                                   \
    auto issue = [&](int kt) {                                                  \
        const int s = kt % STG;                                                 \
        const int k0 = kt * BK;                                                 \
        _Pragma("unroll")                                                       \
        for (int i = 0; i < 4; i++) {                                           \
            const int u = tid + 256 * i;                                        \
            const int row = u >> 3, c8 = (u & 7) * 8;                           \
            cp16(sb + 2 * (s * HSTAGE + row * RSH + c8),                        \
                 (A_) + (size_t)(bm + row) * DD + k0 + c8);                     \
            cp16(sb + 2 * (B_OFF + s * HSTAGE + row * RSH + c8),                \
                 (W_) + (size_t)(bn + row) * DD + k0 + c8);                     \
        }                                                                       \
    };                                                                          \
    issue(0); CP_COMMIT();                                                      \
    issue(1); CP_COMMIT();                                                      \
    for (int kt = 0; kt < NK; kt++) {                                           \
        CP_WAIT1();                                                             \
        __syncthreads();                                                        \
        const int s = kt % STG;                                                 \
        const uint32_t abase = sb + 2 * (s * HSTAGE + a_row * RSH + a_k8);      \
        const uint32_t bbase = sb + 2 * (B_OFF + s * HSTAGE + b_n * RSH + b_k8);\
        _Pragma("unroll")                                                       \
        for (int kk = 0; kk < BK; kk += 16) {                                   \
            uint32_t af[4][4], bf[4][2];                                        \
            _Pragma("unroll")                                                   \
            for (int mi = 0; mi < 4; mi++)                                      \
                ldsm_x4(af[mi], abase + 2 * (mi * 16 * RSH + kk));              \
            _Pragma("unroll")                                                   \
            for (int nj = 0; nj < 2; nj++) {                                    \
                uint32_t t[4];                                                  \
                ldsm_x4(t, bbase + 2 * (nj * 16 * RSH + kk));                   \
                bf[nj * 2][0] = t[0]; bf[nj * 2][1] = t[1];                     \
                bf[nj * 2 + 1][0] = t[2]; bf[nj * 2 + 1][1] = t[3];             \
            }                                                                   \
            _Pragma("unroll")                                                   \
            for (int mi = 0; mi < 4; mi++)                                      \
                _Pragma("unroll")                                               \
                for (int ni = 0; ni < 4; ni++)                                  \
                    mma_f16(acc[mi][ni], af[mi], bf[ni]);                       \
            if (kk == 0) {   /* overlap next-stage issue with remaining MMA */  \
                if (kt + 2 < NK) issue(kt + 2);                                 \
                CP_COMMIT();                                                    \
            }                                                                   \
        }                                                                       \
    }

#define GEMM_PROLOG                                                             \
    extern __shared__ __half hsmem[];                                           \
    const uint32_t sb = smem_u32(hsmem);                                        \
    const int tid = threadIdx.x;                                                \
    const int wid = tid >> 5;                                                   \
    const int lane = tid & 31;                                                  \
    const int r = lane >> 2;                                                    \
    const int c = lane & 3;                                                     \
    const int mw = (wid >> 2) * 64;                                             \
    const int nw = (wid & 3) * 32;                                              \
    const int bm = blockIdx.y * BM;                                             \
    const int bn = blockIdx.x * BN;                                             \
    const int a_row = mw + (lane & 15);                                         \
    const int a_k8  = (lane >> 4) * 8;                                          \
    const int b_n   = nw + ((lane >> 4) << 3) + (lane & 7);                     \
    const int b_k8  = ((lane >> 3) & 1) * 8;                                    \
    float acc[4][4][4];                                                         \
    _Pragma("unroll")                                                           \
    for (int i = 0; i < 4; i++)                                                 \
        _Pragma("unroll")                                                       \
        for (int j = 0; j < 4; j++)                                             \
            _Pragma("unroll")                                                   \
            for (int q = 0; q < 4; q++) acc[i][j][q] = 0.f;

// ---- pre-activation GEMMs: z=0 -> zr (Wr), z=1 -> zi (Wi); fp16 output
__global__ void __launch_bounds__(256, 2)
gemm_pre(const __half* __restrict__ A, const __half* __restrict__ Wbase)
{
    GEMM_PROLOG
    const __half* W = Wbase + (size_t)blockIdx.z * DD * DD;
    __half* Cd = blockIdx.z ? g_zi : g_zr;
    GEMM_MAINLOOP(A, W)

#pragma unroll
    for (int mi = 0; mi < 4; mi++) {
#pragma unroll
        for (int ni = 0; ni < 4; ni++) {
            const int m0 = bm + mw + mi * 16 + r;
            const int n  = bn + nw + ni * 8 + c * 2;
            half2 lo = __floats2half2_rn(acc[mi][ni][0], acc[mi][ni][1]);
            half2 hi = __floats2half2_rn(acc[mi][ni][2], acc[mi][ni][3]);
            *(half2*)(Cd + (size_t)m0 * DD + n) = lo;
            *(half2*)(Cd + (size_t)(m0 + 8) * DD + n) = hi;
        }
    }
}

// ---- gate GEMM: computes zx, reads fp16 zr/zi, writes fp32 a/u
__global__ void __launch_bounds__(256, 2)
gemm_gate(const __half* __restrict__ A, const __half* __restrict__ W,
          const float* __restrict__ br, const float* __restrict__ bi)
{
    GEMM_PROLOG
    GEMM_MAINLOOP(A, W)

#pragma unroll
    for (int mi = 0; mi < 4; mi++) {
#pragma unroll
        for (int ni = 0; ni < 4; ni++) {
            const int m0 = bm + mw + mi * 16 + r;
            const int n  = bn + nw + ni * 8 + c * 2;
            const float br0 = __ldg(br + n), br1 = __ldg(br + n + 1);
            const float bi0 = __ldg(bi + n), bi1 = __ldg(bi + n + 1);
#pragma unroll
            for (int h = 0; h < 2; h++) {
                const size_t idx = (size_t)(m0 + 8 * h) * DD + n;
                float2 zr = __half22float2(*(const half2*)(g_zr + idx));
                float2 zi = __half22float2(*(const half2*)(g_zi + idx));
                float av[2], uv[2];
#pragma unroll
                for (int q = 0; q < 2; q++) {
                    const float zrv = (q ? zr.y : zr.x) + (q ? br1 : br0);
                    const float ziv = (q ? zi.y : zi.x) + (q ? bi1 : bi0);
                    const float rr = 1.f / (1.f + __expf(-zrv));
                    // exp(-softplus(log8*r)) == sigmoid(-log8*r)
                    const float a = 1.f / (1.f + __expf(LOG8F * rr));
                    const float g = sqrtf(fmaxf(1.f - a * a, 1e-6f));
                    const float iv = 1.f / (1.f + __expf(-ziv));
                    av[q] = a;
                    uv[q] = g * iv * acc[mi][ni][h * 2 + q];
                }
                *(float2*)&g_a[idx] = make_float2(av[0], av[1]);
                *(float2*)&g_u[idx] = make_float2(uv[0], uv[1]);
            }
        }
    }
}

// ---------------------------------------------------------------- scan (3-pass)
__global__ void __launch_bounds__(256) scan_pass1() {
    const int g = blockIdx.x * 256 + threadIdx.x;
    const int d = g & (DD - 1);
    const int ch = (g >> 10) & (CH - 1);
    const int b = g >> 16;
    const size_t base = (size_t)b * TT * DD + (size_t)ch * CLEN * DD + d;
    float P = 1.f, Q = 0.f;
#pragma unroll 8
    for (int j = 0; j < CLEN; j++) {
        const float a = g_a[base + (size_t)j * DD];
        const float u = g_u[base + (size_t)j * DD];
        P *= a;
        Q = fmaf(a, Q, u);
    }
    g_P[g] = P;
    g_Q[g] = Q;
}

__global__ void __launch_bounds__(256) scan_pass2(const float* __restrict__ h0,
                                                  float* __restrict__ hlast) {
    const int bd = blockIdx.x * 256 + threadIdx.x;
    const int b = bd >> 10, d = bd & (DD - 1);
    float S = h0[bd];
#pragma unroll
    for (int ch = 0; ch < CH; ch++) {
        const int idx = ((b * CH + ch) << 10) | d;
        g_S[idx] = S;
        S = fmaf(g_P[idx], S, g_Q[idx]);
    }
    hlast[bd] = S;
}

__global__ void __launch_bounds__(256) scan_pass3(float* __restrict__ out) {
    const int g = blockIdx.x * 256 + threadIdx.x;
    const int d = g & (DD - 1);
    const int ch = (g >> 10) & (CH - 1);
    const int b = g >> 16;
    const size_t base = (size_t)b * TT * DD + (size_t)ch * CLEN * DD + d;
    float h = g_S[g];
#pragma unroll 8
    for (int j = 0; j < CLEN; j++) {
        h = fmaf(g_a[base + (size_t)j * DD], h, g_u[base + (size_t)j * DD]);
        out[base + (size_t)j * DD] = h;
    }
}

// ---------------------------------------------------------------- launch
extern "C" void kernel_launch(void* const* d_in, const int* in_sizes, int n_in,
                              void* d_out, int out_size)
{
    const float* x   = (const float*)d_in[0];
    const float* h0  = (const float*)d_in[1];
    const float* W_r = (const float*)d_in[2];
    const float* b_r = (const float*)d_in[3];
    const float* W_i = (const float*)d_in[4];
    const float* b_i = (const float*)d_in[5];
    const float* W_x = (const float*)d_in[6];
    float* out = (float*)d_out;

    __half *xh, *wh;
    cudaGetSymbolAddress((void**)&xh, g_xh);
    cudaGetSymbolAddress((void**)&wh, g_wh);
    __half* wxh = wh + 2 * (size_t)DD * DD;

    cudaFuncSetAttribute(gemm_pre,  cudaFuncAttributeMaxDynamicSharedMemorySize, SMEM_H);
    cudaFuncSetAttribute(gemm_gate, cudaFuncAttributeMaxDynamicSharedMemorySize, SMEM_H);

    cvt_half<<<(int)(TOTL / 4 / 256), 256>>>(x, xh);
    cvt_w3<<<3 * 1024, 256>>>(W_r, W_i, W_x, wh);

    dim3 gridp(DD / BN, MM / BM, 2);   // (8, 128, 2): Wr + Wi merged
    gemm_pre<<<gridp, 256, SMEM_H>>>(xh, wh);
    dim3 grid(DD / BN, MM / BM);       // (8, 128)
    gemm_gate<<<grid, 256, SMEM_H>>>(xh, wxh, b_r, b_i);

    scan_pass1<<<(BD * CH) / 256, 256>>>();
    scan_pass2<<<BD / 256, 256>>>(h0, out + TOTL);
    scan_pass3<<<(BD * CH) / 256, 256>>>(out);
}

// round 12
// speedup vs baseline: 2.4153x; 1.0260x over previous
#include <cuda_runtime.h>
#include <cuda_fp16.h>
#include <cstdint>
#include <math.h>

// ---------------------------------------------------------------- constants
#define BB 4
#define TT 4096
#define DD 1024
#define MM (BB * TT)            // 16384
#define TOTL ((size_t)MM * DD)  // 16777216
#define BD (BB * DD)            // 4096
#define CH 64                   // scan chunks per sequence
#define CLEN (TT / CH)          // 64

#define LOG8F 2.0794415416798357f

// ---------------------------------------------------------------- scratch
__device__ __half g_zr[MM * DD];    // fp16 raw zr
__device__ __half g_zi[MM * DD];    // fp16 raw zi
__device__ __half g_zx[MM * DD];    // fp16 raw zx
__device__ __half g_xh[MM * DD];    // fp16 x
__device__ __half g_wh[3][DD * DD]; // fp16 Wr, Wi, Wx
__device__ float  g_P[BD * CH];
__device__ float  g_Q[BD * CH];
__device__ float  g_S[BD * CH];

// ---------------------------------------------------------------- ptx utils
__device__ __forceinline__ uint32_t smem_u32(const void* p) {
    uint32_t a;
    asm("{ .reg .u64 t; cvta.to.shared.u64 t, %1; cvt.u32.u64 %0, t; }" : "=r"(a) : "l"(p));
    return a;
}
__device__ __forceinline__ void mma_f16(float* d, const uint32_t* a, const uint32_t* b) {
    asm volatile(
        "mma.sync.aligned.m16n8k16.row.col.f32.f16.f16.f32 "
        "{%0,%1,%2,%3}, {%4,%5,%6,%7}, {%8,%9}, {%0,%1,%2,%3};"
        : "+f"(d[0]), "+f"(d[1]), "+f"(d[2]), "+f"(d[3])
        : "r"(a[0]), "r"(a[1]), "r"(a[2]), "r"(a[3]), "r"(b[0]), "r"(b[1]));
}
__device__ __forceinline__ void ldsm_x4(uint32_t* r, uint32_t addr) {
    asm volatile("ldmatrix.sync.aligned.m8n8.x4.shared.b16 {%0,%1,%2,%3}, [%4];"
                 : "=r"(r[0]), "=r"(r[1]), "=r"(r[2]), "=r"(r[3]) : "r"(addr));
}
__device__ __forceinline__ void cp16(uint32_t saddr, const void* g) {
    asm volatile("cp.async.cg.shared.global [%0], [%1], 16;" :: "r"(saddr), "l"(g));
}
#define CP_COMMIT() asm volatile("cp.async.commit_group;" ::: "memory")
#define CP_WAIT1()  asm volatile("cp.async.wait_group 1;" ::: "memory")

// gate math: from raw (zr+br, zi+bi, zx) -> (a, u)
__device__ __forceinline__ void gate_au(float zrv, float ziv, float zx,
                                        float& a, float& u) {
    const float rr = 1.f / (1.f + __expf(-zrv));
    // exp(-softplus(log8*r)) == sigmoid(-log8*r)
    a = 1.f / (1.f + __expf(LOG8F * rr));
    const float g = sqrtf(fmaxf(1.f - a * a, 1e-6f));
    const float iv = 1.f / (1.f + __expf(-ziv));
    u = g * iv * zx;
}

// fp32 -> fp16 pre-conversion (4 floats / thread)
__global__ void __launch_bounds__(256)
cvt_half(const float* __restrict__ src, __half* __restrict__ dst) {
    const size_t i = (size_t)blockIdx.x * 256 + threadIdx.x;
    float4 v = ((const float4*)src)[i];
    half2 h01 = __floats2half2_rn(v.x, v.y);
    half2 h23 = __floats2half2_rn(v.z, v.w);
    ((uint2*)dst)[i] = make_uint2(*(uint32_t*)&h01, *(uint32_t*)&h23);
}
__global__ void __launch_bounds__(256)
cvt_w3(const float* __restrict__ wr, const float* __restrict__ wi,
       const float* __restrict__ wx, __half* __restrict__ dst) {
    const int grp = blockIdx.x >> 10;
    const size_t i = ((size_t)(blockIdx.x & 1023)) * 256 + threadIdx.x;
    const float* src = (grp == 0) ? wr : ((grp == 1) ? wi : wx);
    float4 v = ((const float4*)src)[i];
    half2 h01 = __floats2half2_rn(v.x, v.y);
    half2 h23 = __floats2half2_rn(v.z, v.w);
    ((uint2*)(dst + (size_t)grp * DD * DD))[i] = make_uint2(*(uint32_t*)&h01, *(uint32_t*)&h23);
}

// ================================================================ fp16 GEMM
// C[m,n] = sum_k A[m,k]*W[n,k] (NT), fp16 in / fp32 accum / fp16 out.
// 128x128x64 CTA tile, 8 warps (2Mx4N), 64x32 warp tile, 3-stage cp.async.
// grid.z selects weight matrix and destination (zr / zi / zx).
#define BM 128
#define BN 128
#define BK 64
#define NK (DD / BK)                   // 16
#define STG 3
#define RSH 72                         // halves per smem row (64 + 8 pad)
#define HSTAGE (128 * RSH)             // halves per stage (9216)
#define B_OFF (STG * HSTAGE)           // halves
#define SMEM_H (2 * STG * HSTAGE * 2)  // 110592 bytes

__global__ void __launch_bounds__(256, 2)
gemm3(const __half* __restrict__ A, const __half* __restrict__ Wbase)
{
    extern __shared__ __half hsmem[];
    const uint32_t sb = smem_u32(hsmem);
    const int tid = threadIdx.x;
    const int wid = tid >> 5;
    const int lane = tid & 31;
    const int r = lane >> 2;
    const int c = lane & 3;
    const int mw = (wid >> 2) * 64;
    const int nw = (wid & 3) * 32;
    const int bm = blockIdx.y * BM;
    const int bn = blockIdx.x * BN;
    const int z  = blockIdx.z;

    const __half* W = Wbase + (size_t)z * DD * DD;
    __half* Cd = (z == 0) ? g_zr : ((z == 1) ? g_zi : g_zx);

    const int a_row = mw + (lane & 15);
    const int a_k8  = (lane >> 4) * 8;
    const int b_n   = nw + ((lane >> 4) << 3) + (lane & 7);
    const int b_k8  = ((lane >> 3) & 1) * 8;

    float acc[4][4][4];
#pragma unroll
    for (int i = 0; i < 4; i++)
#pragma unroll
        for (int j = 0; j < 4; j++)
#pragma unroll
            for (int q = 0; q < 4; q++) acc[i][j][q] = 0.f;

    auto issue = [&](int kt) {
        const int s = kt % STG;
        const int k0 = kt * BK;
#pragma unroll
        for (int i = 0; i < 4; i++) {
            const int u = tid + 256 * i;
            const int row = u >> 3, c8 = (u & 7) * 8;
            cp16(sb + 2 * (s * HSTAGE + row * RSH + c8),
                 A + (size_t)(bm + row) * DD + k0 + c8);
            cp16(sb + 2 * (B_OFF + s * HSTAGE + row * RSH + c8),
                 W + (size_t)(bn + row) * DD + k0 + c8);
        }
    };

    issue(0); CP_COMMIT();
    issue(1); CP_COMMIT();

    for (int kt = 0; kt < NK; kt++) {
        CP_WAIT1();
        __syncthreads();
        const int s = kt % STG;
        const uint32_t abase = sb + 2 * (s * HSTAGE + a_row * RSH + a_k8);
        const uint32_t bbase = sb + 2 * (B_OFF + s * HSTAGE + b_n * RSH + b_k8);
#pragma unroll
        for (int kk = 0; kk < BK; kk += 16) {
            uint32_t af[4][4], bf[4][2];
#pragma unroll
            for (int mi = 0; mi < 4; mi++)
                ldsm_x4(af[mi], abase + 2 * (mi * 16 * RSH + kk));
#pragma unroll
            for (int nj = 0; nj < 2; nj++) {
                uint32_t t[4];
                ldsm_x4(t, bbase + 2 * (nj * 16 * RSH + kk));
                bf[nj * 2][0] = t[0]; bf[nj * 2][1] = t[1];
                bf[nj * 2 + 1][0] = t[2]; bf[nj * 2 + 1][1] = t[3];
            }
#pragma unroll
            for (int mi = 0; mi < 4; mi++)
#pragma unroll
                for (int ni = 0; ni < 4; ni++)
                    mma_f16(acc[mi][ni], af[mi], bf[ni]);
            if (kk == 0) {   // overlap next-stage issue with remaining MMA
                if (kt + 2 < NK) issue(kt + 2);
                CP_COMMIT();
            }
        }
    }

    // epilogue: stream fp16 raw results
#pragma unroll
    for (int mi = 0; mi < 4; mi++) {
#pragma unroll
        for (int ni = 0; ni < 4; ni++) {
            const int m0 = bm + mw + mi * 16 + r;
            const int n  = bn + nw + ni * 8 + c * 2;
            half2 lo = __floats2half2_rn(acc[mi][ni][0], acc[mi][ni][1]);
            half2 hi = __floats2half2_rn(acc[mi][ni][2], acc[mi][ni][3]);
            *(half2*)(Cd + (size_t)m0 * DD + n) = lo;
            *(half2*)(Cd + (size_t)(m0 + 8) * DD + n) = hi;
        }
    }
}

// ---------------------------------------------------------------- scan
// pass1: per (b, chunk, d-pair): read zr/zi/zx, gate math, emit (P, Q).
__global__ void __launch_bounds__(256)
scan_pass1(const float* __restrict__ br, const float* __restrict__ bi)
{
    const int g = blockIdx.x * 256 + threadIdx.x;   // 0..131071
    const int d = (g & 511) * 2;
    const int ch = (g >> 9) & (CH - 1);
    const int b = g >> 15;
    const size_t base = ((size_t)b * TT + (size_t)ch * CLEN) * DD + d;
    const float2 br2 = *(const float2*)(br + d);
    const float2 bi2 = *(const float2*)(bi + d);

    float P0 = 1.f, Q0 = 0.f, P1 = 1.f, Q1 = 0.f;
#pragma unroll 8
    for (int j = 0; j < CLEN; j++) {
        const size_t idx = base + (size_t)j * DD;
        float2 zr = __half22float2(*(const half2*)(g_zr + idx));
        float2 zi = __half22float2(*(const half2*)(g_zi + idx));
        float2 zx = __half22float2(*(const half2*)(g_zx + idx));
        float a0, u0, a1, u1;
        gate_au(zr.x + br2.x, zi.x + bi2.x, zx.x, a0, u0);
        gate_au(zr.y + br2.y, zi.y + bi2.y, zx.y, a1, u1);
        P0 *= a0; Q0 = fmaf(a0, Q0, u0);
        P1 *= a1; Q1 = fmaf(a1, Q1, u1);
    }
    const int o = ((b * CH + ch) << 10) | d;
    *(float2*)&g_P[o] = make_float2(P0, P1);
    *(float2*)&g_Q[o] = make_float2(Q0, Q1);
}

// pass2: serial over chunks per (b, d); emits chunk start states + h_last.
__global__ void __launch_bounds__(256)
scan_pass2(const float* __restrict__ h0, float* __restrict__ hlast)
{
    const int bd = blockIdx.x * 256 + threadIdx.x;
    const int b = bd >> 10, d = bd & (DD - 1);
    float S = h0[bd];
#pragma unroll
    for (int ch = 0; ch < CH; ch++) {
        const int idx = ((b * CH + ch) << 10) | d;
        g_S[idx] = S;
        S = fmaf(g_P[idx], S, g_Q[idx]);
    }
    hlast[bd] = S;
}

// pass3: re-read raw z's, recompute gate, scan from known start, write out.
__global__ void __launch_bounds__(256)
scan_pass3(const float* __restrict__ br, const float* __restrict__ bi,
           float* __restrict__ out)
{
    const int g = blockIdx.x * 256 + threadIdx.x;
    const int d = (g & 511) * 2;
    const int ch = (g >> 9) & (CH - 1);
    const int b = g >> 15;
    const size_t base = ((size_t)b * TT + (size_t)ch * CLEN) * DD + d;
    const float2 br2 = *(const float2*)(br + d);
    const float2 bi2 = *(const float2*)(bi + d);

    const int o = ((b * CH + ch) << 10) | d;
    float2 h = *(const float2*)&g_S[o];
#pragma unroll 8
    for (int j = 0; j < CLEN; j++) {
        const size_t idx = base + (size_t)j * DD;
        float2 zr = __half22float2(*(const half2*)(g_zr + idx));
        float2 zi = __half22float2(*(const half2*)(g_zi + idx));
        float2 zx = __half22float2(*(const half2*)(g_zx + idx));
        float a0, u0, a1, u1;
        gate_au(zr.x + br2.x, zi.x + bi2.x, zx.x, a0, u0);
        gate_au(zr.y + br2.y, zi.y + bi2.y, zx.y, a1, u1);
        h.x = fmaf(a0, h.x, u0);
        h.y = fmaf(a1, h.y, u1);
        *(float2*)(out + idx) = h;
    }
}

// ---------------------------------------------------------------- launch
extern "C" void kernel_launch(void* const* d_in, const int* in_sizes, int n_in,
                              void* d_out, int out_size)
{
    const float* x   = (const float*)d_in[0];
    const float* h0  = (const float*)d_in[1];
    const float* W_r = (const float*)d_in[2];
    const float* b_r = (const float*)d_in[3];
    const float* W_i = (const float*)d_in[4];
    const float* b_i = (const float*)d_in[5];
    const float* W_x = (const float*)d_in[6];
    float* out = (float*)d_out;

    __half *xh, *wh;
    cudaGetSymbolAddress((void**)&xh, g_xh);
    cudaGetSymbolAddress((void**)&wh, g_wh);

    cudaFuncSetAttribute(gemm3, cudaFuncAttributeMaxDynamicSharedMemorySize, SMEM_H);

    cvt_half<<<(int)(TOTL / 4 / 256), 256>>>(x, xh);
    cvt_w3<<<3 * 1024, 256>>>(W_r, W_i, W_x, wh);

    dim3 grid(DD / BN, MM / BM, 3);   // (8, 128, 3): all three GEMMs
    gemm3<<<grid, 256, SMEM_H>>>(xh, wh);

    scan_pass1<<<(BB * CH * DD / 2) / 256, 256>>>(b_r, b_i);
    scan_pass2<<<BD / 256, 256>>>(h0, out + TOTL);
    scan_pass3<<<(BB * CH * DD / 2) / 256, 256>>>(b_r, b_i, out);
}

// round 13
// speedup vs baseline: 2.4862x; 1.0293x over previous
#include <cuda_runtime.h>
#include <cuda_fp16.h>
#include <cstdint>
#include <math.h>

// ---------------------------------------------------------------- constants
#define BB 4
#define TT 4096
#define DD 1024
#define MM (BB * TT)            // 16384
#define TOTL ((size_t)MM * DD)  // 16777216
#define BD (BB * DD)            // 4096
#define CH 128                  // scan chunks per sequence
#define CLEN (TT / CH)          // 32

#define LOG8F 2.0794415416798357f

// ---------------------------------------------------------------- scratch
__device__ __half g_zr[MM * DD];    // fp16 raw zr
__device__ __half g_zi[MM * DD];    // fp16 raw zi
__device__ __half g_zx[MM * DD];    // fp16 raw zx
__device__ __half g_xh[MM * DD];    // fp16 x
__device__ __half g_wh[3][DD * DD]; // fp16 Wr, Wi, Wx
__device__ float  g_P[BD * CH];
__device__ float  g_Q[BD * CH];
__device__ float  g_S[BD * CH];

// ---------------------------------------------------------------- ptx utils
__device__ __forceinline__ uint32_t smem_u32(const void* p) {
    uint32_t a;
    asm("{ .reg .u64 t; cvta.to.shared.u64 t, %1; cvt.u32.u64 %0, t; }" : "=r"(a) : "l"(p));
    return a;
}
__device__ __forceinline__ void mma_f16(float* d, const uint32_t* a, const uint32_t* b) {
    asm volatile(
        "mma.sync.aligned.m16n8k16.row.col.f32.f16.f16.f32 "
        "{%0,%1,%2,%3}, {%4,%5,%6,%7}, {%8,%9}, {%0,%1,%2,%3};"
        : "+f"(d[0]), "+f"(d[1]), "+f"(d[2]), "+f"(d[3])
        : "r"(a[0]), "r"(a[1]), "r"(a[2]), "r"(a[3]), "r"(b[0]), "r"(b[1]));
}
__device__ __forceinline__ void ldsm_x4(uint32_t* r, uint32_t addr) {
    asm volatile("ldmatrix.sync.aligned.m8n8.x4.shared.b16 {%0,%1,%2,%3}, [%4];"
                 : "=r"(r[0]), "=r"(r[1]), "=r"(r[2]), "=r"(r[3]) : "r"(addr));
}
__device__ __forceinline__ void cp16(uint32_t saddr, const void* g) {
    asm volatile("cp.async.cg.shared.global [%0], [%1], 16;" :: "r"(saddr), "l"(g));
}
#define CP_COMMIT() asm volatile("cp.async.commit_group;" ::: "memory")
#define CP_WAIT1()  asm volatile("cp.async.wait_group 1;" ::: "memory")

// gate math: from raw (zr+br, zi+bi, zx) -> (a, u)
__device__ __forceinline__ void gate_au(float zrv, float ziv, float zx,
                                        float& a, float& u) {
    const float rr = 1.f / (1.f + __expf(-zrv));
    // exp(-softplus(log8*r)) == sigmoid(-log8*r)
    a = 1.f / (1.f + __expf(LOG8F * rr));
    const float g = sqrtf(fmaxf(1.f - a * a, 1e-6f));
    const float iv = 1.f / (1.f + __expf(-ziv));
    u = g * iv * zx;
}

// fp32 -> fp16 pre-conversion (4 floats / thread)
__global__ void __launch_bounds__(256)
cvt_half(const float* __restrict__ src, __half* __restrict__ dst) {
    const size_t i = (size_t)blockIdx.x * 256 + threadIdx.x;
    float4 v = ((const float4*)src)[i];
    half2 h01 = __floats2half2_rn(v.x, v.y);
    half2 h23 = __floats2half2_rn(v.z, v.w);
    ((uint2*)dst)[i] = make_uint2(*(uint32_t*)&h01, *(uint32_t*)&h23);
}
__global__ void __launch_bounds__(256)
cvt_w3(const float* __restrict__ wr, const float* __restrict__ wi,
       const float* __restrict__ wx, __half* __restrict__ dst) {
    const int grp = blockIdx.x >> 10;
    const size_t i = ((size_t)(blockIdx.x & 1023)) * 256 + threadIdx.x;
    const float* src = (grp == 0) ? wr : ((grp == 1) ? wi : wx);
    float4 v = ((const float4*)src)[i];
    half2 h01 = __floats2half2_rn(v.x, v.y);
    half2 h23 = __floats2half2_rn(v.z, v.w);
    ((uint2*)(dst + (size_t)grp * DD * DD))[i] = make_uint2(*(uint32_t*)&h01, *(uint32_t*)&h23);
}

// ================================================================ fp16 GEMM
// C[m,n] = sum_k A[m,k]*W[n,k] (NT), fp16 in / fp32 accum / fp16 out.
// 128x128x64 CTA tile, 8 warps (2Mx4N), 64x32 warp tile, 3-stage cp.async.
// grid.z selects weight matrix and destination (zr / zi / zx).
#define BM 128
#define BN 128
#define BK 64
#define NK (DD / BK)                   // 16
#define STG 3
#define RSH 72                         // halves per smem row (64 + 8 pad)
#define HSTAGE (128 * RSH)             // halves per stage (9216)
#define B_OFF (STG * HSTAGE)           // halves
#define SMEM_H (2 * STG * HSTAGE * 2)  // 110592 bytes

__global__ void __launch_bounds__(256, 2)
gemm3(const __half* __restrict__ A, const __half* __restrict__ Wbase)
{
    extern __shared__ __half hsmem[];
    const uint32_t sb = smem_u32(hsmem);
    const int tid = threadIdx.x;
    const int wid = tid >> 5;
    const int lane = tid & 31;
    const int r = lane >> 2;
    const int c = lane & 3;
    const int mw = (wid >> 2) * 64;
    const int nw = (wid & 3) * 32;
    const int bm = blockIdx.y * BM;
    const int bn = blockIdx.x * BN;
    const int z  = blockIdx.z;

    const __half* W = Wbase + (size_t)z * DD * DD;
    __half* Cd = (z == 0) ? g_zr : ((z == 1) ? g_zi : g_zx);

    const int a_row = mw + (lane & 15);
    const int a_k8  = (lane >> 4) * 8;
    const int b_n   = nw + ((lane >> 4) << 3) + (lane & 7);
    const int b_k8  = ((lane >> 3) & 1) * 8;

    float acc[4][4][4];
#pragma unroll
    for (int i = 0; i < 4; i++)
#pragma unroll
        for (int j = 0; j < 4; j++)
#pragma unroll
            for (int q = 0; q < 4; q++) acc[i][j][q] = 0.f;

    auto issue = [&](int kt) {
        const int s = kt % STG;
        const int k0 = kt * BK;
#pragma unroll
        for (int i = 0; i < 4; i++) {
            const int u = tid + 256 * i;
            const int row = u >> 3, c8 = (u & 7) * 8;
            cp16(sb + 2 * (s * HSTAGE + row * RSH + c8),
                 A + (size_t)(bm + row) * DD + k0 + c8);
            cp16(sb + 2 * (B_OFF + s * HSTAGE + row * RSH + c8),
                 W + (size_t)(bn + row) * DD + k0 + c8);
        }
    };

    issue(0); CP_COMMIT();
    issue(1); CP_COMMIT();

    for (int kt = 0; kt < NK; kt++) {
        CP_WAIT1();
        __syncthreads();
        const int s = kt % STG;
        const uint32_t abase = sb + 2 * (s * HSTAGE + a_row * RSH + a_k8);
        const uint32_t bbase = sb + 2 * (B_OFF + s * HSTAGE + b_n * RSH + b_k8);
#pragma unroll
        for (int kk = 0; kk < BK; kk += 16) {
            uint32_t af[4][4], bf[4][2];
#pragma unroll
            for (int mi = 0; mi < 4; mi++)
                ldsm_x4(af[mi], abase + 2 * (mi * 16 * RSH + kk));
#pragma unroll
            for (int nj = 0; nj < 2; nj++) {
                uint32_t t[4];
                ldsm_x4(t, bbase + 2 * (nj * 16 * RSH + kk));
                bf[nj * 2][0] = t[0]; bf[nj * 2][1] = t[1];
                bf[nj * 2 + 1][0] = t[2]; bf[nj * 2 + 1][1] = t[3];
            }
#pragma unroll
            for (int mi = 0; mi < 4; mi++)
#pragma unroll
                for (int ni = 0; ni < 4; ni++)
                    mma_f16(acc[mi][ni], af[mi], bf[ni]);
            if (kk == 0) {   // overlap next-stage issue with remaining MMA
                if (kt + 2 < NK) issue(kt + 2);
                CP_COMMIT();
            }
        }
    }

    // epilogue: stream fp16 raw results
#pragma unroll
    for (int mi = 0; mi < 4; mi++) {
#pragma unroll
        for (int ni = 0; ni < 4; ni++) {
            const int m0 = bm + mw + mi * 16 + r;
            const int n  = bn + nw + ni * 8 + c * 2;
            half2 lo = __floats2half2_rn(acc[mi][ni][0], acc[mi][ni][1]);
            half2 hi = __floats2half2_rn(acc[mi][ni][2], acc[mi][ni][3]);
            *(half2*)(Cd + (size_t)m0 * DD + n) = lo;
            *(half2*)(Cd + (size_t)(m0 + 8) * DD + n) = hi;
        }
    }
}

// ---------------------------------------------------------------- scan
// pass1: per (b, chunk, d-pair): read zr/zi/zx, gate math, emit (P, Q).
__global__ void __launch_bounds__(256)
scan_pass1(const float* __restrict__ br, const float* __restrict__ bi)
{
    const int g = blockIdx.x * 256 + threadIdx.x;   // 0..BB*CH*512-1
    const int d = (g & 511) * 2;
    const int ch = (g >> 9) & (CH - 1);
    const int b = g >> 16;                           // 9 + 7 bits below
    const size_t base = ((size_t)b * TT + (size_t)ch * CLEN) * DD + d;
    const float2 br2 = *(const float2*)(br + d);
    const float2 bi2 = *(const float2*)(bi + d);

    float P0 = 1.f, Q0 = 0.f, P1 = 1.f, Q1 = 0.f;
#pragma unroll 8
    for (int j = 0; j < CLEN; j++) {
        const size_t idx = base + (size_t)j * DD;
        float2 zr = __half22float2(*(const half2*)(g_zr + idx));
        float2 zi = __half22float2(*(const half2*)(g_zi + idx));
        float2 zx = __half22float2(*(const half2*)(g_zx + idx));
        float a0, u0, a1, u1;
        gate_au(zr.x + br2.x, zi.x + bi2.x, zx.x, a0, u0);
        gate_au(zr.y + br2.y, zi.y + bi2.y, zx.y, a1, u1);
        P0 *= a0; Q0 = fmaf(a0, Q0, u0);
        P1 *= a1; Q1 = fmaf(a1, Q1, u1);
    }
    const int o = ((b * CH + ch) << 10) | d;
    *(float2*)&g_P[o] = make_float2(P0, P1);
    *(float2*)&g_Q[o] = make_float2(Q0, Q1);
}

// pass2: serial over chunks per (b, d); emits chunk start states + h_last.
__global__ void __launch_bounds__(256)
scan_pass2(const float* __restrict__ h0, float* __restrict__ hlast)
{
    const int bd = blockIdx.x * 256 + threadIdx.x;
    const int b = bd >> 10, d = bd & (DD - 1);
    float S = h0[bd];
#pragma unroll
    for (int ch = 0; ch < CH; ch++) {
        const int idx = ((b * CH + ch) << 10) | d;
        g_S[idx] = S;
        S = fmaf(g_P[idx], S, g_Q[idx]);
    }
    hlast[bd] = S;
}

// pass3: re-read raw z's, recompute gate, scan from known start, write out.
__global__ void __launch_bounds__(256)
scan_pass3(const float* __restrict__ br, const float* __restrict__ bi,
           float* __restrict__ out)
{
    const int g = blockIdx.x * 256 + threadIdx.x;
    const int d = (g & 511) * 2;
    const int ch = (g >> 9) & (CH - 1);
    const int b = g >> 16;
    const size_t base = ((size_t)b * TT + (size_t)ch * CLEN) * DD + d;
    const float2 br2 = *(const float2*)(br + d);
    const float2 bi2 = *(const float2*)(bi + d);

    const int o = ((b * CH + ch) << 10) | d;
    float2 h = *(const float2*)&g_S[o];
#pragma unroll 8
    for (int j = 0; j < CLEN; j++) {
        const size_t idx = base + (size_t)j * DD;
        float2 zr = __half22float2(*(const half2*)(g_zr + idx));
        float2 zi = __half22float2(*(const half2*)(g_zi + idx));
        float2 zx = __half22float2(*(const half2*)(g_zx + idx));
        float a0, u0, a1, u1;
        gate_au(zr.x + br2.x, zi.x + bi2.x, zx.x, a0, u0);
        gate_au(zr.y + br2.y, zi.y + bi2.y, zx.y, a1, u1);
        h.x = fmaf(a0, h.x, u0);
        h.y = fmaf(a1, h.y, u1);
        *(float2*)(out + idx) = h;
    }
}

// ---------------------------------------------------------------- launch
extern "C" void kernel_launch(void* const* d_in, const int* in_sizes, int n_in,
                              void* d_out, int out_size)
{
    const float* x   = (const float*)d_in[0];
    const float* h0  = (const float*)d_in[1];
    const float* W_r = (const float*)d_in[2];
    const float* b_r = (const float*)d_in[3];
    const float* W_i = (const float*)d_in[4];
    const float* b_i = (const float*)d_in[5];
    const float* W_x = (const float*)d_in[6];
    float* out = (float*)d_out;

    __half *xh, *wh;
    cudaGetSymbolAddress((void**)&xh, g_xh);
    cudaGetSymbolAddress((void**)&wh, g_wh);

    cudaFuncSetAttribute(gemm3, cudaFuncAttributeMaxDynamicSharedMemorySize, SMEM_H);

    cvt_half<<<(int)(TOTL / 4 / 256), 256>>>(x, xh);
    cvt_w3<<<3 * 1024, 256>>>(W_r, W_i, W_x, wh);

    dim3 grid(DD / BN, MM / BM, 3);   // (8, 128, 3): all three GEMMs
    gemm3<<<grid, 256, SMEM_H>>>(xh, wh);

    scan_pass1<<<(BB * CH * DD / 2) / 256, 256>>>(b_r, b_i);
    scan_pass2<<<BD / 256, 256>>>(h0, out + TOTL);
    scan_pass3<<<(BB * CH * DD / 2) / 256, 256>>>(b_r, b_i, out);
}

// round 14
// speedup vs baseline: 2.7056x; 1.0882x over previous
#include <cuda_runtime.h>
#include <cuda_fp16.h>
#include <cstdint>
#include <math.h>

// ---------------------------------------------------------------- constants
#define BB 4
#define TT 4096
#define DD 1024
#define MM (BB * TT)            // 16384
#define TOTL ((size_t)MM * DD)  // 16777216
#define BD (BB * DD)            // 4096
#define CH 128                  // scan chunks per sequence
#define CLEN (TT / CH)          // 32

#define LOG8F 2.0794415416798357f

// ---------------------------------------------------------------- scratch
__device__ __half g_zr[MM * DD];    // fp16 raw zr
__device__ __half g_zi[MM * DD];    // fp16 raw zi
__device__ __half g_zx[MM * DD];    // fp16 raw zx
__device__ __half g_af[MM * DD];    // fp16 decay a (pass1 -> pass3)
__device__ __half g_uf[MM * DD];    // fp16 input term u (pass1 -> pass3)
__device__ __half g_xh[MM * DD];    // fp16 x
__device__ __half g_wh[3][DD * DD]; // fp16 Wr, Wi, Wx
__device__ float  g_P[BD * CH];
__device__ float  g_Q[BD * CH];
__device__ float  g_S[BD * CH];

// ---------------------------------------------------------------- ptx utils
__device__ __forceinline__ uint32_t smem_u32(const void* p) {
    uint32_t a;
    asm("{ .reg .u64 t; cvta.to.shared.u64 t, %1; cvt.u32.u64 %0, t; }" : "=r"(a) : "l"(p));
    return a;
}
__device__ __forceinline__ void mma_f16(float* d, const uint32_t* a, const uint32_t* b) {
    asm volatile(
        "mma.sync.aligned.m16n8k16.row.col.f32.f16.f16.f32 "
        "{%0,%1,%2,%3}, {%4,%5,%6,%7}, {%8,%9}, {%0,%1,%2,%3};"
        : "+f"(d[0]), "+f"(d[1]), "+f"(d[2]), "+f"(d[3])
        : "r"(a[0]), "r"(a[1]), "r"(a[2]), "r"(a[3]), "r"(b[0]), "r"(b[1]));
}
__device__ __forceinline__ void ldsm_x4(uint32_t* r, uint32_t addr) {
    asm volatile("ldmatrix.sync.aligned.m8n8.x4.shared.b16 {%0,%1,%2,%3}, [%4];"
                 : "=r"(r[0]), "=r"(r[1]), "=r"(r[2]), "=r"(r[3]) : "r"(addr));
}
__device__ __forceinline__ void cp16(uint32_t saddr, const void* g) {
    asm volatile("cp.async.cg.shared.global [%0], [%1], 16;" :: "r"(saddr), "l"(g));
}
#define CP_COMMIT() asm volatile("cp.async.commit_group;" ::: "memory")
#define CP_WAIT1()  asm volatile("cp.async.wait_group 1;" ::: "memory")

__device__ __forceinline__ float tanh_a(float x) {
    float y;
    asm("tanh.approx.f32 %0, %1;" : "=f"(y) : "f"(x));
    return y;
}

// gate math via tanh.approx: sigmoid(x) = 0.5 + 0.5*tanh(x/2)
__device__ __forceinline__ void gate_au(float zrv, float ziv, float zx,
                                        float& a, float& u) {
    const float r = fmaf(tanh_a(0.5f * zrv), 0.5f, 0.5f);
    // a = sigmoid(-log8 * r) = 0.5 - 0.5*tanh(log8*r/2)
    a = fmaf(tanh_a(0.5f * LOG8F * r), -0.5f, 0.5f);
    const float g = sqrtf(fmaxf(1.f - a * a, 1e-6f));
    const float iv = fmaf(tanh_a(0.5f * ziv), 0.5f, 0.5f);
    u = g * iv * zx;
}

// fp32 -> fp16 pre-conversion (4 floats / thread)
__global__ void __launch_bounds__(256)
cvt_half(const float* __restrict__ src, __half* __restrict__ dst) {
    const size_t i = (size_t)blockIdx.x * 256 + threadIdx.x;
    float4 v = ((const float4*)src)[i];
    half2 h01 = __floats2half2_rn(v.x, v.y);
    half2 h23 = __floats2half2_rn(v.z, v.w);
    ((uint2*)dst)[i] = make_uint2(*(uint32_t*)&h01, *(uint32_t*)&h23);
}
__global__ void __launch_bounds__(256)
cvt_w3(const float* __restrict__ wr, const float* __restrict__ wi,
       const float* __restrict__ wx, __half* __restrict__ dst) {
    const int grp = blockIdx.x >> 10;
    const size_t i = ((size_t)(blockIdx.x & 1023)) * 256 + threadIdx.x;
    const float* src = (grp == 0) ? wr : ((grp == 1) ? wi : wx);
    float4 v = ((const float4*)src)[i];
    half2 h01 = __floats2half2_rn(v.x, v.y);
    half2 h23 = __floats2half2_rn(v.z, v.w);
    ((uint2*)(dst + (size_t)grp * DD * DD))[i] = make_uint2(*(uint32_t*)&h01, *(uint32_t*)&h23);
}

// ================================================================ fp16 GEMM
// C[m,n] = sum_k A[m,k]*W[n,k] (NT), fp16 in / fp32 accum / fp16 out.
// 128x128x64 CTA tile, 8 warps (2Mx4N), 64x32 warp tile, 3-stage cp.async.
// grid.z selects weight matrix and destination (zr / zi / zx).
#define BM 128
#define BN 128
#define BK 64
#define NK (DD / BK)                   // 16
#define STG 3
#define RSH 72                         // halves per smem row (64 + 8 pad)
#define HSTAGE (128 * RSH)             // halves per stage (9216)
#define B_OFF (STG * HSTAGE)           // halves
#define SMEM_H (2 * STG * HSTAGE * 2)  // 110592 bytes

__global__ void __launch_bounds__(256, 2)
gemm3(const __half* __restrict__ A, const __half* __restrict__ Wbase)
{
    extern __shared__ __half hsmem[];
    const uint32_t sb = smem_u32(hsmem);
    const int tid = threadIdx.x;
    const int wid = tid >> 5;
    const int lane = tid & 31;
    const int r = lane >> 2;
    const int c = lane & 3;
    const int mw = (wid >> 2) * 64;
    const int nw = (wid & 3) * 32;
    const int bm = blockIdx.y * BM;
    const int bn = blockIdx.x * BN;
    const int z  = blockIdx.z;

    const __half* W = Wbase + (size_t)z * DD * DD;
    __half* Cd = (z == 0) ? g_zr : ((z == 1) ? g_zi : g_zx);

    const int a_row = mw + (lane & 15);
    const int a_k8  = (lane >> 4) * 8;
    const int b_n   = nw + ((lane >> 4) << 3) + (lane & 7);
    const int b_k8  = ((lane >> 3) & 1) * 8;

    float acc[4][4][4];
#pragma unroll
    for (int i = 0; i < 4; i++)
#pragma unroll
        for (int j = 0; j < 4; j++)
#pragma unroll
            for (int q = 0; q < 4; q++) acc[i][j][q] = 0.f;

    auto issue = [&](int kt) {
        const int s = kt % STG;
        const int k0 = kt * BK;
#pragma unroll
        for (int i = 0; i < 4; i++) {
            const int u = tid + 256 * i;
            const int row = u >> 3, c8 = (u & 7) * 8;
            cp16(sb + 2 * (s * HSTAGE + row * RSH + c8),
                 A + (size_t)(bm + row) * DD + k0 + c8);
            cp16(sb + 2 * (B_OFF + s * HSTAGE + row * RSH + c8),
                 W + (size_t)(bn + row) * DD + k0 + c8);
        }
    };

    issue(0); CP_COMMIT();
    issue(1); CP_COMMIT();

    for (int kt = 0; kt < NK; kt++) {
        CP_WAIT1();
        __syncthreads();
        const int s = kt % STG;
        const uint32_t abase = sb + 2 * (s * HSTAGE + a_row * RSH + a_k8);
        const uint32_t bbase = sb + 2 * (B_OFF + s * HSTAGE + b_n * RSH + b_k8);
#pragma unroll
        for (int kk = 0; kk < BK; kk += 16) {
            uint32_t af[4][4], bf[4][2];
#pragma unroll
            for (int mi = 0; mi < 4; mi++)
                ldsm_x4(af[mi], abase + 2 * (mi * 16 * RSH + kk));
#pragma unroll
            for (int nj = 0; nj < 2; nj++) {
                uint32_t t[4];
                ldsm_x4(t, bbase + 2 * (nj * 16 * RSH + kk));
                bf[nj * 2][0] = t[0]; bf[nj * 2][1] = t[1];
                bf[nj * 2 + 1][0] = t[2]; bf[nj * 2 + 1][1] = t[3];
            }
#pragma unroll
            for (int mi = 0; mi < 4; mi++)
#pragma unroll
                for (int ni = 0; ni < 4; ni++)
                    mma_f16(acc[mi][ni], af[mi], bf[ni]);
            if (kk == 0) {   // overlap next-stage issue with remaining MMA
                if (kt + 2 < NK) issue(kt + 2);
                CP_COMMIT();
            }
        }
    }

    // epilogue: stream fp16 raw results
#pragma unroll
    for (int mi = 0; mi < 4; mi++) {
#pragma unroll
        for (int ni = 0; ni < 4; ni++) {
            const int m0 = bm + mw + mi * 16 + r;
            const int n  = bn + nw + ni * 8 + c * 2;
            half2 lo = __floats2half2_rn(acc[mi][ni][0], acc[mi][ni][1]);
            half2 hi = __floats2half2_rn(acc[mi][ni][2], acc[mi][ni][3]);
            *(half2*)(Cd + (size_t)m0 * DD + n) = lo;
            *(half2*)(Cd + (size_t)(m0 + 8) * DD + n) = hi;
        }
    }
}

// ---------------------------------------------------------------- scan
// pass1: read zr/zi/zx, gate math ONCE, store fp16 (a,u), emit (P, Q).
__global__ void __launch_bounds__(256)
scan_pass1(const float* __restrict__ br, const float* __restrict__ bi)
{
    const int g = blockIdx.x * 256 + threadIdx.x;   // 0..BB*CH*512-1
    const int d = (g & 511) * 2;
    const int ch = (g >> 9) & (CH - 1);
    const int b = g >> 16;
    const size_t base = ((size_t)b * TT + (size_t)ch * CLEN) * DD + d;
    const float2 br2 = *(const float2*)(br + d);
    const float2 bi2 = *(const float2*)(bi + d);

    float P0 = 1.f, Q0 = 0.f, P1 = 1.f, Q1 = 0.f;
#pragma unroll 8
    for (int j = 0; j < CLEN; j++) {
        const size_t idx = base + (size_t)j * DD;
        float2 zr = __half22float2(*(const half2*)(g_zr + idx));
        float2 zi = __half22float2(*(const half2*)(g_zi + idx));
        float2 zx = __half22float2(*(const half2*)(g_zx + idx));
        float a0, u0, a1, u1;
        gate_au(zr.x + br2.x, zi.x + bi2.x, zx.x, a0, u0);
        gate_au(zr.y + br2.y, zi.y + bi2.y, zx.y, a1, u1);
        *(half2*)(g_af + idx) = __floats2half2_rn(a0, a1);
        *(half2*)(g_uf + idx) = __floats2half2_rn(u0, u1);
        P0 *= a0; Q0 = fmaf(a0, Q0, u0);
        P1 *= a1; Q1 = fmaf(a1, Q1, u1);
    }
    const int o = ((b * CH + ch) << 10) | d;
    *(float2*)&g_P[o] = make_float2(P0, P1);
    *(float2*)&g_Q[o] = make_float2(Q0, Q1);
}

// pass2: serial over chunks per (b, d); emits chunk start states + h_last.
__global__ void __launch_bounds__(256)
scan_pass2(const float* __restrict__ h0, float* __restrict__ hlast)
{
    const int bd = blockIdx.x * 256 + threadIdx.x;
    const int b = bd >> 10, d = bd & (DD - 1);
    float S = h0[bd];
#pragma unroll
    for (int ch = 0; ch < CH; ch++) {
        const int idx = ((b * CH + ch) << 10) | d;
        g_S[idx] = S;
        S = fmaf(g_P[idx], S, g_Q[idx]);
    }
    hlast[bd] = S;
}

// pass3: read fp16 (a,u), scan from known start, write out. No gate math.
__global__ void __launch_bounds__(256)
scan_pass3(float* __restrict__ out)
{
    const int g = blockIdx.x * 256 + threadIdx.x;
    const int d = (g & 511) * 2;
    const int ch = (g >> 9) & (CH - 1);
    const int b = g >> 16;
    const size_t base = ((size_t)b * TT + (size_t)ch * CLEN) * DD + d;

    const int o = ((b * CH + ch) << 10) | d;
    float2 h = *(const float2*)&g_S[o];
#pragma unroll 8
    for (int j = 0; j < CLEN; j++) {
        const size_t idx = base + (size_t)j * DD;
        float2 a = __half22float2(*(const half2*)(g_af + idx));
        float2 u = __half22float2(*(const half2*)(g_uf + idx));
        h.x = fmaf(a.x, h.x, u.x);
        h.y = fmaf(a.y, h.y, u.y);
        *(float2*)(out + idx) = h;
    }
}

// ---------------------------------------------------------------- launch
extern "C" void kernel_launch(void* const* d_in, const int* in_sizes, int n_in,
                              void* d_out, int out_size)
{
    const float* x   = (const float*)d_in[0];
    const float* h0  = (const float*)d_in[1];
    const float* W_r = (const float*)d_in[2];
    const float* b_r = (const float*)d_in[3];
    const float* W_i = (const float*)d_in[4];
    const float* b_i = (const float*)d_in[5];
    const float* W_x = (const float*)d_in[6];
    float* out = (float*)d_out;

    __half *xh, *wh;
    cudaGetSymbolAddress((void**)&xh, g_xh);
    cudaGetSymbolAddress((void**)&wh, g_wh);

    cudaFuncSetAttribute(gemm3, cudaFuncAttributeMaxDynamicSharedMemorySize, SMEM_H);

    cvt_half<<<(int)(TOTL / 4 / 256), 256>>>(x, xh);
    cvt_w3<<<3 * 1024, 256>>>(W_r, W_i, W_x, wh);

    dim3 grid(DD / BN, MM / BM, 3);   // (8, 128, 3): all three GEMMs
    gemm3<<<grid, 256, SMEM_H>>>(xh, wh);

    scan_pass1<<<(BB * CH * DD / 2) / 256, 256>>>(b_r, b_i);
    scan_pass2<<<BD / 256, 256>>>(h0, out + TOTL);
    scan_pass3<<<(BB * CH * DD / 2) / 256, 256>>>(out);
}